// round 13
// baseline (speedup 1.0000x reference)
#include <cuda_runtime.h>
#include <cuda_fp16.h>
#include <cstdint>

#define NB   8
#define CC   256
#define CQK  32
#define LL   4096
#define BI   64
#define BJ   64
#define NJT  (LL / BJ)          // 64 j-tiles
#define INVLN2 1.4426950408889634f

// ---------------- scratch (device globals) ----------------------------------
__device__ __half g_Wh [320 * 256];                 // fused weights fp16-hi, (o, c)
__device__ __half g_Wql[64 * 256];                  // fp16-lo residual, q/k rows only
__device__ __half g_qh [NB * LL * CQK];             // (N, L, 32) token-major fp16-hi
__device__ __half g_ql [NB * LL * CQK];
__device__ __half g_kh [NB * LL * CQK];             // (N, L, 32) fp16-hi (scaled 1/ln2)
__device__ __half g_kl [NB * LL * CQK];
__device__ __half g_v  [(size_t)NB * CC * LL];      // (N, C, L) fp16, l contiguous

// ---------------- helpers ----------------------------------------------------
__device__ __forceinline__ uint32_t smem_u32(const void* p) {
    uint32_t a;
    asm("{ .reg .u64 t; cvta.to.shared.u64 t, %1; cvt.u32.u64 %0, t; }" : "=r"(a) : "l"(p));
    return a;
}
__device__ __forceinline__ void cp_async16(uint32_t dst, const void* src) {
    asm volatile("cp.async.cg.shared.global [%0], [%1], 16;"
                 :: "r"(dst), "l"((unsigned long long)__cvta_generic_to_global(src)) : "memory");
}
#define CP_COMMIT() asm volatile("cp.async.commit_group;" ::: "memory")
#define CP_WAIT0()  asm volatile("cp.async.wait_group 0;" ::: "memory")
#define CP_WAIT1()  asm volatile("cp.async.wait_group 1;" ::: "memory")

// mbarrier (sm_80+/sm_90 baseline PTX; no arch-'a' features)
#define MBARRIER_INIT(mbar, cnt) \
    asm volatile("mbarrier.init.shared.b64 [%0], %1;" :: "r"((uint32_t)(mbar)), "r"((uint32_t)(cnt)) : "memory")
#define MBAR_ARRIVE(mbar) \
    asm volatile("mbarrier.arrive.shared::cta.b64 _, [%0];" :: "r"((uint32_t)(mbar)) : "memory")
// NOTE: .noinc is load-bearing (default form pre-increments -> deadlock).
#define CP_MBAR_ARRIVE(mbar) \
    asm volatile("cp.async.mbarrier.arrive.noinc.shared::cta.b64 [%0];" :: "r"((uint32_t)(mbar)) : "memory")
#define MBARRIER_WAIT_PARITY(mbar, parity) do { \
    uint32_t _m = (uint32_t)(mbar); uint32_t _p = (uint32_t)(parity); uint32_t _d; \
    asm volatile("{\n\t.reg .pred p;\n\t" \
        "mbarrier.try_wait.parity.acquire.cta.shared::cta.b64 p, [%1], %2;\n\t" \
        "selp.b32 %0, 1, 0, p;\n\t}" : "=r"(_d) : "r"(_m), "r"(_p) : "memory"); \
    if (!_d) { \
        asm volatile("{\n\t.reg .pred P1;\n\t" \
            "WAIT_LOOP_%=:\n\t" \
            "mbarrier.try_wait.parity.acquire.cta.shared::cta.b64 P1, [%0], %1, 0x989680;\n\t" \
            "@P1 bra.uni WAIT_DONE_%=;\n\t" \
            "bra.uni WAIT_LOOP_%=;\n\t" \
            "WAIT_DONE_%=:\n\t}" :: "r"(_m), "r"(_p) : "memory"); \
    } \
} while (0)

__device__ __forceinline__ uint32_t h2u(__half2 h) { return *reinterpret_cast<uint32_t*>(&h); }
__device__ __forceinline__ float ex2f(float x) {
    float r;
    asm("ex2.approx.f32 %0, %1;" : "=f"(r) : "f"(x));
    return r;
}
__device__ __forceinline__ void ldsm_x4(uint32_t& r0, uint32_t& r1, uint32_t& r2, uint32_t& r3,
                                        uint32_t addr) {
    asm volatile("ldmatrix.sync.aligned.m8n8.x4.shared.b16 {%0,%1,%2,%3}, [%4];"
                 : "=r"(r0), "=r"(r1), "=r"(r2), "=r"(r3) : "r"(addr));
}
__device__ __forceinline__ void ldsm_x4a(uint32_t r[4], uint32_t addr) {
    ldsm_x4(r[0], r[1], r[2], r[3], addr);
}
__device__ __forceinline__ void mma_f16(float c[4], const uint32_t a[4],
                                        uint32_t b0, uint32_t b1) {
    asm("mma.sync.aligned.m16n8k16.row.col.f32.f16.f16.f32 "
        "{%0,%1,%2,%3}, {%4,%5,%6,%7}, {%8,%9}, {%0,%1,%2,%3};"
        : "+f"(c[0]), "+f"(c[1]), "+f"(c[2]), "+f"(c[3])
        : "r"(a[0]), "r"(a[1]), "r"(a[2]), "r"(a[3]), "r"(b0), "r"(b1));
}
// fp16-accumulator mma: D(f16x2[2]) += A(f16) * B(f16)
__device__ __forceinline__ void mma_f16acc(uint32_t c[2], const uint32_t a[4],
                                           uint32_t b0, uint32_t b1) {
    asm("mma.sync.aligned.m16n8k16.row.col.f16.f16.f16.f16 "
        "{%0,%1}, {%2,%3,%4,%5}, {%6,%7}, {%0,%1};"
        : "+r"(c[0]), "+r"(c[1])
        : "r"(a[0]), "r"(a[1]), "r"(a[2]), "r"(a[3]), "r"(b0), "r"(b1));
}

// ---------------- kernel 1: weight prep (fp16 hi + q/k lo residual) ----------
__global__ void wtrans_kernel(const float* __restrict__ Wq,
                              const float* __restrict__ Wk,
                              const float* __restrict__ Wv) {
    int idx = blockIdx.x * 256 + threadIdx.x;
    if (idx >= 320 * 256) return;
    int o = idx >> 8, c = idx & 255;
    float v;
    if (o < 32)       v = Wq[o * 256 + c];
    else if (o < 64)  v = Wk[(o - 32) * 256 + c];
    else              v = Wv[(o - 64) * 256 + c];
    __half h = __float2half_rn(v);
    g_Wh[o * 256 + c] = h;
    if (o < 64) g_Wql[o * 256 + c] = __float2half_rn(v - __half2float(h));
}

// ---------------- kernel 2: tensor-core fused QKV projection ------------------
#define PJ_XH 0
#define PJ_XL 33792
#define PJ_WH 67584        // 3 slots x 5120
#define PJ_WL 82944        // 3 slots x 5120 (q/k CTAs only)
#define PROJ_SMEM 98304

__global__ __launch_bounds__(128, 2)
void proj_kernel(const float* __restrict__ x,
                 const float* __restrict__ bq,
                 const float* __restrict__ bk,
                 const float* __restrict__ bv) {
    extern __shared__ char sm[];
    const uint32_t smb = smem_u32(sm);
    const int tid = threadIdx.x;
    const int wid = tid >> 5, lane = tid & 31;
    const int g = lane >> 2, m = lane & 3;
    const int n = blockIdx.z;
    const int oidx = blockIdx.y;
    const int l0 = blockIdx.x * 64;
    const int obase = oidx * 64;
    const bool qk = (oidx == 0);

    auto issueW = [&](int r, int slot) {
        #pragma unroll
        for (int k = 0; k < 2; k++) {
            int idx = tid * 2 + k;          // 0..255
            int row = idx >> 2, seg = idx & 3;
            cp_async16(smb + PJ_WH + slot * 5120 + row * 80 + seg * 16,
                       g_Wh + (obase + row) * 256 + r * 32 + seg * 8);
            if (qk)
                cp_async16(smb + PJ_WL + slot * 5120 + row * 80 + seg * 16,
                           g_Wql + row * 256 + r * 32 + seg * 8);
        }
        CP_COMMIT();
    };
    issueW(0, 0);
    issueW(1, 1);

    {
        const float* xb = x + ((size_t)n << 20) + l0;
        const int l = tid & 63, p0 = tid >> 6;
        #pragma unroll 4
        for (int i = 0; i < 64; i++) {
            int p = p0 + 2 * i;
            int c = 2 * p;
            float f0 = __ldg(&xb[(size_t)c * 4096 + l]);
            float f1 = __ldg(&xb[(size_t)(c + 1) * 4096 + l]);
            __half h0 = __float2half_rn(f0), h1 = __float2half_rn(f1);
            __half e0 = __float2half_rn(f0 - __half2float(h0));
            __half e1 = __float2half_rn(f1 - __half2float(h1));
            *(uint32_t*)(sm + PJ_XH + l * 528 + p * 4) = h2u(__halves2half2(h0, h1));
            *(uint32_t*)(sm + PJ_XL + l * 528 + p * 4) = h2u(__halves2half2(e0, e1));
        }
    }

    float C[8][4];
    #pragma unroll
    for (int og = 0; og < 8; og++)
        #pragma unroll
        for (int e = 0; e < 4; e++) C[og][e] = 0.f;

    const uint32_t aoffA = (uint32_t)((lane & 15) * 528 + (lane >> 4) * 16);
    const uint32_t aoffB = (uint32_t)((lane & 7) * 80 + (lane >> 3) * 16);
    const uint32_t abase = smb + (uint32_t)(wid * 16) * 528;

    for (int r = 0; r < 8; r++) {
        const int slot = r % 3;
        if (r == 7) { CP_WAIT0(); } else { CP_WAIT1(); }
        __syncthreads();
        if (r + 2 < 8) issueW(r + 2, (r + 2) % 3);

        uint32_t axh0[4], axh1[4], axl0[4], axl1[4];
        ldsm_x4a(axh0, abase + PJ_XH + r * 64 + aoffA);
        ldsm_x4a(axh1, abase + PJ_XH + r * 64 + 32 + aoffA);
        ldsm_x4a(axl0, abase + PJ_XL + r * 64 + aoffA);
        ldsm_x4a(axl1, abase + PJ_XL + r * 64 + 32 + aoffA);

        const uint32_t wb  = smb + PJ_WH + slot * 5120;
        const uint32_t wlb = smb + PJ_WL + slot * 5120;
        #pragma unroll
        for (int og = 0; og < 8; og++) {
            uint32_t b0, b1, b2, b3;
            ldsm_x4(b0, b1, b2, b3, wb + og * 640 + aoffB);
            mma_f16(C[og], axh0, b0, b1);
            mma_f16(C[og], axl0, b0, b1);
            mma_f16(C[og], axh1, b2, b3);
            mma_f16(C[og], axl1, b2, b3);
            if (qk) {
                uint32_t c0, c1, c2, c3;
                ldsm_x4(c0, c1, c2, c3, wlb + og * 640 + aoffB);
                mma_f16(C[og], axh0, c0, c1);
                mma_f16(C[og], axh1, c2, c3);
            }
        }
    }
    __syncthreads();

    if (qk) {
        #pragma unroll
        for (int og = 0; og < 8; og++) {
            int ol = og * 8 + 2 * m;
            bool isq = (ol < 32);
            float sc = isq ? 1.0f : INVLN2;
            const float* bias = isq ? bq : bk;
            int bo = isq ? ol : ol - 32;
            float b0 = __ldg(&bias[bo]), b1 = __ldg(&bias[bo + 1]);
            uint32_t* dsth = (uint32_t*)(isq ? g_qh : g_kh);
            uint32_t* dstl = (uint32_t*)(isq ? g_ql : g_kl);
            int col = (isq ? og * 4 : (og - 4) * 4) + m;
            #pragma unroll
            for (int rr = 0; rr < 2; rr++) {
                float f0 = (C[og][2 * rr]     + b0) * sc;
                float f1 = (C[og][2 * rr + 1] + b1) * sc;
                __half h0 = __float2half_rn(f0), h1 = __float2half_rn(f1);
                __half e0 = __float2half_rn(f0 - __half2float(h0));
                __half e1 = __float2half_rn(f1 - __half2float(h1));
                size_t lg = (size_t)(n << 12) + l0 + wid * 16 + g + 8 * rr;
                dsth[lg * 16 + col] = h2u(__halves2half2(h0, h1));
                dstl[lg * 16 + col] = h2u(__halves2half2(e0, e1));
            }
        }
    } else {
        __half* bo = (__half*)sm;            // [64 o][72 l]
        const int vb0 = (oidx - 1) * 64;
        #pragma unroll
        for (int og = 0; og < 8; og++) {
            int ol = og * 8 + 2 * m;
            float b0 = __ldg(&bv[vb0 + ol]), b1 = __ldg(&bv[vb0 + ol + 1]);
            int lg = wid * 16 + g;
            bo[ol * 72 + lg]           = __float2half_rn(C[og][0] + b0);
            bo[(ol + 1) * 72 + lg]     = __float2half_rn(C[og][1] + b1);
            bo[ol * 72 + lg + 8]       = __float2half_rn(C[og][2] + b0);
            bo[(ol + 1) * 72 + lg + 8] = __float2half_rn(C[og][3] + b1);
        }
        __syncthreads();
        const int o = tid >> 1, lh = tid & 1;
        const uint4* src = (const uint4*)(sm + o * 144 + lh * 64);
        uint4* dst = (uint4*)(g_v + (((size_t)(n * CC + vb0 + o)) << 12) + l0 + lh * 32);
        #pragma unroll
        for (int i = 0; i < 4; i++) dst[i] = src[i];
    }
}

// ---------------- kernel 3: BJ=64 skewed flash attention, f16-accum PV -------
#define OFF_QH 0            // [64][40] fp16
#define OFF_QL 5120
#define OFF_K  10240        // 2 slots x 10240: [KH 64][40] then [KL 64][40]
#define OFF_V  30720        // 2 slots x 36864: [256][72] fp16
#define OFF_MB 104448       // full[0..1] at +0, empty[0..1] at +16
#define ATTN_SMEM 104704

__device__ __forceinline__ void loadK(uint32_t smb, int n, int j0, int slot, int tid) {
    const uint32_t kbase = smb + OFF_K + slot * 10240;
    #pragma unroll
    for (int it = 0; it < 4; it++) {
        int idx = it * 128 + tid;        // 0..511
        int hl = idx >> 8;
        int r  = (idx >> 2) & 63;
        int s  = idx & 3;
        const __half* src = (hl ? g_kl : g_kh) + ((size_t)((n << 12) + j0 + r)) * 32 + s * 8;
        cp_async16(kbase + hl * 5120 + r * 80 + s * 16, src);
    }
}
__device__ __forceinline__ void loadV(uint32_t smb, int n, int j0, int slot, int tid) {
    const uint32_t vbase = smb + OFF_V + slot * 36864;
    #pragma unroll
    for (int it = 0; it < 16; it++) {
        int idx = it * 128 + tid;        // 0..2047
        int cr = idx >> 3;               // 0..255
        int s  = idx & 7;
        const __half* src = g_v + (((size_t)n * CC + cr) << 12) + j0 + s * 8;
        cp_async16(vbase + cr * 144 + s * 16, src);
    }
}

__global__ __launch_bounds__(128, 2)
void attn_kernel(const float* __restrict__ x,
                 const float* __restrict__ gamma,
                 float* __restrict__ out) {
    extern __shared__ char sm[];
    const uint32_t smb = smem_u32(sm);
    const int tid  = threadIdx.x;
    const int wid  = tid >> 5, lane = tid & 31;
    const int g    = lane >> 2, m = lane & 3;
    const int iw   = wid * 16;
    const int n    = blockIdx.y;
    const int i0   = blockIdx.x * BI;

    const uint32_t aoffK = (uint32_t)((lane & 7) * 80 + (lane >> 3) * 16);
    const uint32_t aoffV = (uint32_t)((lane & 7) * 144 + (lane >> 3) * 16);
    const uint32_t mb_full  = smb + OFF_MB;
    const uint32_t mb_empty = smb + OFF_MB + 16;

    if (tid == 0) {
        #pragma unroll
        for (int s = 0; s < 2; s++) {
            MBARRIER_INIT(mb_full + 8 * s, 128);
            MBARRIER_INIT(mb_empty + 8 * s, 4);
        }
    }

    // ---- Q tile via plain ld/st ----
    #pragma unroll
    for (int it = 0; it < 4; it++) {
        int idx  = it * 128 + tid;          // 0..511
        int half = idx >> 8;
        int r    = (idx >> 2) & 63;
        int s    = idx & 3;
        const __half* src = (half ? g_ql : g_qh) + ((size_t)((n << 12) + i0 + r)) * 32 + s * 8;
        uint4 v = *(const uint4*)src;
        *(uint4*)(sm + (half ? OFF_QL : OFF_QH) + r * 80 + s * 16) = v;
    }
    __syncthreads();   // mbarrier init + Q visible

    // ---- prologue: fill slots 0,1 (tiles 0,1) ----
    #pragma unroll
    for (int t = 0; t < 2; t++) {
        loadK(smb, n, t * BJ, t, tid);
        loadV(smb, n, t * BJ, t, tid);
        CP_MBAR_ARRIVE(mb_full + 8 * t);
    }

    // ---- Q fragments ----
    uint32_t qh[2][4], ql[2][4];
    {
        const uint32_t* QHw = (const uint32_t*)(sm + OFF_QH);
        const uint32_t* QLw = (const uint32_t*)(sm + OFF_QL);
        #pragma unroll
        for (int kc = 0; kc < 2; kc++) {
            qh[kc][0] = QHw[(iw + g)     * 20 + 8 * kc + m];
            qh[kc][1] = QHw[(iw + g + 8) * 20 + 8 * kc + m];
            qh[kc][2] = QHw[(iw + g)     * 20 + 8 * kc + 4 + m];
            qh[kc][3] = QHw[(iw + g + 8) * 20 + 8 * kc + 4 + m];
            ql[kc][0] = QLw[(iw + g)     * 20 + 8 * kc + m];
            ql[kc][1] = QLw[(iw + g + 8) * 20 + 8 * kc + m];
            ql[kc][2] = QLw[(iw + g)     * 20 + 8 * kc + 4 + m];
            ql[kc][3] = QLw[(iw + g + 8) * 20 + 8 * kc + 4 + m];
        }
    }

    float O[32][4];
    #pragma unroll
    for (int nt = 0; nt < 32; nt++)
        #pragma unroll
        for (int e = 0; e < 4; e++) O[nt][e] = 0.f;
    float mr0 = -1e30f, mr1 = -1e30f, lr0 = 0.f, lr1 = 0.f;

    for (int jt = 0; jt < NJT; jt++) {
        const int s = jt & 1;

        // ---- per-warp prefetch of tile jt+1 into the other slot ----
        if (jt >= 1 && jt + 1 < NJT) {
            const int t2 = jt + 1;
            const int s2 = t2 & 1;
            MBARRIER_WAIT_PARITY(mb_empty + 8 * s2, (uint32_t)(((t2 >> 1) - 1) & 1));
            loadK(smb, n, t2 * BJ, s2, tid);
            loadV(smb, n, t2 * BJ, s2, tid);
            CP_MBAR_ARRIVE(mb_full + 8 * s2);
        }

        // ---- wait data ----
        MBARRIER_WAIT_PARITY(mb_full + 8 * s, (uint32_t)((jt >> 1) & 1));

        // ---- S = Q K^T (3-term fp16 split), 64 j per tile ----
        const uint32_t kb = smb + OFF_K + s * 10240;
        float C[8][4];
        #pragma unroll
        for (int nt = 0; nt < 8; nt++) {
            C[nt][0] = C[nt][1] = C[nt][2] = C[nt][3] = 0.f;
            uint32_t h0, h1, h2, h3, e0, e1, e2, e3;
            ldsm_x4(h0, h1, h2, h3, kb + nt * 640 + aoffK);
            ldsm_x4(e0, e1, e2, e3, kb + 5120 + nt * 640 + aoffK);
            mma_f16(C[nt], qh[0], h0, h1);  mma_f16(C[nt], ql[0], h0, h1);  mma_f16(C[nt], qh[0], e0, e1);
            mma_f16(C[nt], qh[1], h2, h3);  mma_f16(C[nt], ql[1], h2, h3);  mma_f16(C[nt], qh[1], e2, e3);
        }

        // ---- softmax, exp2 domain ----
        float t0 = -1e30f, t1 = -1e30f;
        #pragma unroll
        for (int nt = 0; nt < 8; nt++) {
            t0 = fmaxf(t0, fmaxf(C[nt][0], C[nt][1]));
            t1 = fmaxf(t1, fmaxf(C[nt][2], C[nt][3]));
        }
        t0 = fmaxf(t0, __shfl_xor_sync(0xffffffffu, t0, 1));
        t0 = fmaxf(t0, __shfl_xor_sync(0xffffffffu, t0, 2));
        t1 = fmaxf(t1, __shfl_xor_sync(0xffffffffu, t1, 1));
        t1 = fmaxf(t1, __shfl_xor_sync(0xffffffffu, t1, 2));
        float mn0 = fmaxf(mr0, t0), mn1 = fmaxf(mr1, t1);
        float al0 = ex2f(mr0 - mn0), al1 = ex2f(mr1 - mn1);
        mr0 = mn0; mr1 = mn1;

        uint32_t P[8][2];
        float rs0 = 0.f, rs1 = 0.f;
        #pragma unroll
        for (int nt = 0; nt < 8; nt++) {
            float p0 = ex2f(C[nt][0] - mn0), p1 = ex2f(C[nt][1] - mn0);
            float p2 = ex2f(C[nt][2] - mn1), p3 = ex2f(C[nt][3] - mn1);
            __half2 h01 = __floats2half2_rn(p0, p1);
            __half2 h23 = __floats2half2_rn(p2, p3);
            P[nt][0] = h2u(h01); P[nt][1] = h2u(h23);
            float2 f01 = __half22float2(h01), f23 = __half22float2(h23);
            rs0 += f01.x + f01.y; rs1 += f23.x + f23.y;
        }
        rs0 += __shfl_xor_sync(0xffffffffu, rs0, 1);
        rs0 += __shfl_xor_sync(0xffffffffu, rs0, 2);
        rs1 += __shfl_xor_sync(0xffffffffu, rs1, 1);
        rs1 += __shfl_xor_sync(0xffffffffu, rs1, 2);
        lr0 = lr0 * al0 + rs0;
        lr1 = lr1 * al1 + rs1;

        if (__any_sync(0xffffffffu, (al0 != 1.f) || (al1 != 1.f))) {
            #pragma unroll
            for (int nt = 0; nt < 32; nt++) {
                O[nt][0] *= al0; O[nt][1] *= al0;
                O[nt][2] *= al1; O[nt][3] *= al1;
            }
        }

        // ---- O += P V  (fp16-accum PV, promoted to f32 per 8-nt group) ----
        uint32_t pa[4][4];
        #pragma unroll
        for (int kc = 0; kc < 4; kc++) {
            pa[kc][0] = P[2 * kc][0];     pa[kc][1] = P[2 * kc][1];
            pa[kc][2] = P[2 * kc + 1][0]; pa[kc][3] = P[2 * kc + 1][1];
        }
        const uint32_t vb = smb + OFF_V + s * 36864;
        #pragma unroll
        for (int ntg = 0; ntg < 4; ntg++) {
            uint32_t Oh[8][2];
            #pragma unroll
            for (int q2 = 0; q2 < 8; q2++) { Oh[q2][0] = 0u; Oh[q2][1] = 0u; }
            #pragma unroll
            for (int q2 = 0; q2 < 8; q2++) {
                const int nt = ntg * 8 + q2;
                uint32_t b00, b01, b10, b11, c00, c01, c10, c11;
                ldsm_x4(b00, b01, b10, b11, vb + nt * 1152 + aoffV);
                ldsm_x4(c00, c01, c10, c11, vb + nt * 1152 + 64 + aoffV);
                mma_f16acc(Oh[q2], pa[0], b00, b01);
                mma_f16acc(Oh[q2], pa[1], b10, b11);
                mma_f16acc(Oh[q2], pa[2], c00, c01);
                mma_f16acc(Oh[q2], pa[3], c10, c11);
            }
            #pragma unroll
            for (int q2 = 0; q2 < 8; q2++) {
                const int nt = ntg * 8 + q2;
                float2 f01 = __half22float2(*reinterpret_cast<__half2*>(&Oh[q2][0]));
                float2 f23 = __half22float2(*reinterpret_cast<__half2*>(&Oh[q2][1]));
                O[nt][0] += f01.x; O[nt][1] += f01.y;
                O[nt][2] += f23.x; O[nt][3] += f23.y;
            }
        }

        // ---- this warp done reading slot s ----
        __syncwarp();
        if (lane == 0) MBAR_ARRIVE(mb_empty + 8 * s);
    }

    // ---- epilogue ----
    const float linv0 = 1.0f / lr0;
    const float linv1 = 1.0f / lr1;
    const float gam = __ldg(gamma);
    #pragma unroll
    for (int nt = 0; nt < 32; nt++) {
        #pragma unroll
        for (int e = 0; e < 4; e++) {
            int c   = 8 * nt + 2 * m + (e & 1);
            int row = iw + g + 8 * (e >> 1);
            size_t idx = (((size_t)(n * CC + c)) << 12) + i0 + row;
            float o = O[nt][e] * ((e >> 1) ? linv1 : linv0);
            out[idx] = gam * o + __ldg(&x[idx]);
        }
    }
}

// ---------------- launch -----------------------------------------------------
extern "C" void kernel_launch(void* const* d_in, const int* in_sizes, int n_in,
                              void* d_out, int out_size) {
    const float* x     = (const float*)d_in[0];
    const float* Wq    = (const float*)d_in[1];
    const float* bq    = (const float*)d_in[2];
    const float* Wk    = (const float*)d_in[3];
    const float* bk    = (const float*)d_in[4];
    const float* Wv    = (const float*)d_in[5];
    const float* bv    = (const float*)d_in[6];
    const float* gamma = (const float*)d_in[7];
    float* out = (float*)d_out;

    cudaFuncSetAttribute(proj_kernel, cudaFuncAttributeMaxDynamicSharedMemorySize, PROJ_SMEM);
    cudaFuncSetAttribute(attn_kernel, cudaFuncAttributeMaxDynamicSharedMemorySize, ATTN_SMEM);

    wtrans_kernel<<<320, 256>>>(Wq, Wk, Wv);
    proj_kernel<<<dim3(LL / 64, 5, NB), 128, PROJ_SMEM>>>(x, bq, bk, bv);
    attn_kernel<<<dim3(LL / BI, NB), 128, ATTN_SMEM>>>(x, gamma, out);
}

// round 14
// speedup vs baseline: 1.2706x; 1.2706x over previous
#include <cuda_runtime.h>
#include <cuda_fp16.h>
#include <cstdint>

#define NB   8
#define CC   256
#define CQK  32
#define LL   4096
#define BI   64
#define BJ   64
#define NJT  (LL / BJ)          // 64 j-tiles
#define INVLN2 1.4426950408889634f

// ---------------- scratch (device globals) ----------------------------------
__device__ __half g_Wh [320 * 256];                 // fused weights fp16-hi, (o, c)
__device__ __half g_Wql[64 * 256];                  // fp16-lo residual, q/k rows only
__device__ __half g_qh [NB * LL * CQK];             // (N, L, 32) token-major fp16-hi
__device__ __half g_ql [NB * LL * CQK];
__device__ __half g_kh [NB * LL * CQK];             // (N, L, 32) fp16-hi (scaled 1/ln2)
__device__ __half g_kl [NB * LL * CQK];
__device__ __half g_v  [(size_t)NB * CC * LL];      // (N, C, L) fp16, l contiguous

// ---------------- helpers ----------------------------------------------------
__device__ __forceinline__ uint32_t smem_u32(const void* p) {
    uint32_t a;
    asm("{ .reg .u64 t; cvta.to.shared.u64 t, %1; cvt.u32.u64 %0, t; }" : "=r"(a) : "l"(p));
    return a;
}
__device__ __forceinline__ void cp_async16(uint32_t dst, const void* src) {
    asm volatile("cp.async.cg.shared.global [%0], [%1], 16;"
                 :: "r"(dst), "l"((unsigned long long)__cvta_generic_to_global(src)) : "memory");
}
#define CP_COMMIT() asm volatile("cp.async.commit_group;" ::: "memory")
#define CP_WAIT0()  asm volatile("cp.async.wait_group 0;" ::: "memory")
#define CP_WAIT1()  asm volatile("cp.async.wait_group 1;" ::: "memory")

// mbarrier (sm_80+/sm_90 baseline PTX; no arch-'a' features)
#define MBARRIER_INIT(mbar, cnt) \
    asm volatile("mbarrier.init.shared.b64 [%0], %1;" :: "r"((uint32_t)(mbar)), "r"((uint32_t)(cnt)) : "memory")
#define MBAR_ARRIVE(mbar) \
    asm volatile("mbarrier.arrive.shared::cta.b64 _, [%0];" :: "r"((uint32_t)(mbar)) : "memory")
// NOTE: .noinc is load-bearing (default form pre-increments -> deadlock).
#define CP_MBAR_ARRIVE(mbar) \
    asm volatile("cp.async.mbarrier.arrive.noinc.shared::cta.b64 [%0];" :: "r"((uint32_t)(mbar)) : "memory")
#define MBARRIER_WAIT_PARITY(mbar, parity) do { \
    uint32_t _m = (uint32_t)(mbar); uint32_t _p = (uint32_t)(parity); uint32_t _d; \
    asm volatile("{\n\t.reg .pred p;\n\t" \
        "mbarrier.try_wait.parity.acquire.cta.shared::cta.b64 p, [%1], %2;\n\t" \
        "selp.b32 %0, 1, 0, p;\n\t}" : "=r"(_d) : "r"(_m), "r"(_p) : "memory"); \
    if (!_d) { \
        asm volatile("{\n\t.reg .pred P1;\n\t" \
            "WAIT_LOOP_%=:\n\t" \
            "mbarrier.try_wait.parity.acquire.cta.shared::cta.b64 P1, [%0], %1, 0x989680;\n\t" \
            "@P1 bra.uni WAIT_DONE_%=;\n\t" \
            "bra.uni WAIT_LOOP_%=;\n\t" \
            "WAIT_DONE_%=:\n\t}" :: "r"(_m), "r"(_p) : "memory"); \
    } \
} while (0)

__device__ __forceinline__ uint32_t h2u(__half2 h) { return *reinterpret_cast<uint32_t*>(&h); }
__device__ __forceinline__ float ex2f(float x) {
    float r;
    asm("ex2.approx.f32 %0, %1;" : "=f"(r) : "f"(x));
    return r;
}
__device__ __forceinline__ void ldsm_x4(uint32_t& r0, uint32_t& r1, uint32_t& r2, uint32_t& r3,
                                        uint32_t addr) {
    asm volatile("ldmatrix.sync.aligned.m8n8.x4.shared.b16 {%0,%1,%2,%3}, [%4];"
                 : "=r"(r0), "=r"(r1), "=r"(r2), "=r"(r3) : "r"(addr));
}
__device__ __forceinline__ void ldsm_x4a(uint32_t r[4], uint32_t addr) {
    ldsm_x4(r[0], r[1], r[2], r[3], addr);
}
__device__ __forceinline__ void mma_f16(float c[4], const uint32_t a[4],
                                        uint32_t b0, uint32_t b1) {
    asm("mma.sync.aligned.m16n8k16.row.col.f32.f16.f16.f32 "
        "{%0,%1,%2,%3}, {%4,%5,%6,%7}, {%8,%9}, {%0,%1,%2,%3};"
        : "+f"(c[0]), "+f"(c[1]), "+f"(c[2]), "+f"(c[3])
        : "r"(a[0]), "r"(a[1]), "r"(a[2]), "r"(a[3]), "r"(b0), "r"(b1));
}

// ---------------- kernel 1: weight prep (fp16 hi + q/k lo residual) ----------
__global__ void wtrans_kernel(const float* __restrict__ Wq,
                              const float* __restrict__ Wk,
                              const float* __restrict__ Wv) {
    int idx = blockIdx.x * 256 + threadIdx.x;
    if (idx >= 320 * 256) return;
    int o = idx >> 8, c = idx & 255;
    float v;
    if (o < 32)       v = Wq[o * 256 + c];
    else if (o < 64)  v = Wk[(o - 32) * 256 + c];
    else              v = Wv[(o - 64) * 256 + c];
    __half h = __float2half_rn(v);
    g_Wh[o * 256 + c] = h;
    if (o < 64) g_Wql[o * 256 + c] = __float2half_rn(v - __half2float(h));
}

// ---------------- kernel 2: tensor-core fused QKV projection ------------------
#define PJ_XH 0
#define PJ_XL 33792
#define PJ_WH 67584        // 3 slots x 5120
#define PJ_WL 82944        // 3 slots x 5120 (q/k CTAs only)
#define PROJ_SMEM 98304

__global__ __launch_bounds__(128, 2)
void proj_kernel(const float* __restrict__ x,
                 const float* __restrict__ bq,
                 const float* __restrict__ bk,
                 const float* __restrict__ bv,
                 int n0) {
    extern __shared__ char sm[];
    const uint32_t smb = smem_u32(sm);
    const int tid = threadIdx.x;
    const int wid = tid >> 5, lane = tid & 31;
    const int g = lane >> 2, m = lane & 3;
    const int n = n0 + blockIdx.z;
    const int oidx = blockIdx.y;
    const int l0 = blockIdx.x * 64;
    const int obase = oidx * 64;
    const bool qk = (oidx == 0);

    auto issueW = [&](int r, int slot) {
        #pragma unroll
        for (int k = 0; k < 2; k++) {
            int idx = tid * 2 + k;          // 0..255
            int row = idx >> 2, seg = idx & 3;
            cp_async16(smb + PJ_WH + slot * 5120 + row * 80 + seg * 16,
                       g_Wh + (obase + row) * 256 + r * 32 + seg * 8);
            if (qk)
                cp_async16(smb + PJ_WL + slot * 5120 + row * 80 + seg * 16,
                           g_Wql + row * 256 + r * 32 + seg * 8);
        }
        CP_COMMIT();
    };
    issueW(0, 0);
    issueW(1, 1);

    {
        const float* xb = x + ((size_t)n << 20) + l0;
        const int l = tid & 63, p0 = tid >> 6;
        #pragma unroll 4
        for (int i = 0; i < 64; i++) {
            int p = p0 + 2 * i;
            int c = 2 * p;
            float f0 = __ldg(&xb[(size_t)c * 4096 + l]);
            float f1 = __ldg(&xb[(size_t)(c + 1) * 4096 + l]);
            __half h0 = __float2half_rn(f0), h1 = __float2half_rn(f1);
            __half e0 = __float2half_rn(f0 - __half2float(h0));
            __half e1 = __float2half_rn(f1 - __half2float(h1));
            *(uint32_t*)(sm + PJ_XH + l * 528 + p * 4) = h2u(__halves2half2(h0, h1));
            *(uint32_t*)(sm + PJ_XL + l * 528 + p * 4) = h2u(__halves2half2(e0, e1));
        }
    }

    float C[8][4];
    #pragma unroll
    for (int og = 0; og < 8; og++)
        #pragma unroll
        for (int e = 0; e < 4; e++) C[og][e] = 0.f;

    const uint32_t aoffA = (uint32_t)((lane & 15) * 528 + (lane >> 4) * 16);
    const uint32_t aoffB = (uint32_t)((lane & 7) * 80 + (lane >> 3) * 16);
    const uint32_t abase = smb + (uint32_t)(wid * 16) * 528;

    for (int r = 0; r < 8; r++) {
        const int slot = r % 3;
        if (r == 7) { CP_WAIT0(); } else { CP_WAIT1(); }
        __syncthreads();
        if (r + 2 < 8) issueW(r + 2, (r + 2) % 3);

        uint32_t axh0[4], axh1[4], axl0[4], axl1[4];
        ldsm_x4a(axh0, abase + PJ_XH + r * 64 + aoffA);
        ldsm_x4a(axh1, abase + PJ_XH + r * 64 + 32 + aoffA);
        ldsm_x4a(axl0, abase + PJ_XL + r * 64 + aoffA);
        ldsm_x4a(axl1, abase + PJ_XL + r * 64 + 32 + aoffA);

        const uint32_t wb  = smb + PJ_WH + slot * 5120;
        const uint32_t wlb = smb + PJ_WL + slot * 5120;
        #pragma unroll
        for (int og = 0; og < 8; og++) {
            uint32_t b0, b1, b2, b3;
            ldsm_x4(b0, b1, b2, b3, wb + og * 640 + aoffB);
            mma_f16(C[og], axh0, b0, b1);
            mma_f16(C[og], axl0, b0, b1);
            mma_f16(C[og], axh1, b2, b3);
            mma_f16(C[og], axl1, b2, b3);
            if (qk) {
                uint32_t c0, c1, c2, c3;
                ldsm_x4(c0, c1, c2, c3, wlb + og * 640 + aoffB);
                mma_f16(C[og], axh0, c0, c1);
                mma_f16(C[og], axh1, c2, c3);
            }
        }
    }
    __syncthreads();

    if (qk) {
        #pragma unroll
        for (int og = 0; og < 8; og++) {
            int ol = og * 8 + 2 * m;
            bool isq = (ol < 32);
            float sc = isq ? 1.0f : INVLN2;
            const float* bias = isq ? bq : bk;
            int bo = isq ? ol : ol - 32;
            float b0 = __ldg(&bias[bo]), b1 = __ldg(&bias[bo + 1]);
            uint32_t* dsth = (uint32_t*)(isq ? g_qh : g_kh);
            uint32_t* dstl = (uint32_t*)(isq ? g_ql : g_kl);
            int col = (isq ? og * 4 : (og - 4) * 4) + m;
            #pragma unroll
            for (int rr = 0; rr < 2; rr++) {
                float f0 = (C[og][2 * rr]     + b0) * sc;
                float f1 = (C[og][2 * rr + 1] + b1) * sc;
                __half h0 = __float2half_rn(f0), h1 = __float2half_rn(f1);
                __half e0 = __float2half_rn(f0 - __half2float(h0));
                __half e1 = __float2half_rn(f1 - __half2float(h1));
                size_t lg = (size_t)(n << 12) + l0 + wid * 16 + g + 8 * rr;
                dsth[lg * 16 + col] = h2u(__halves2half2(h0, h1));
                dstl[lg * 16 + col] = h2u(__halves2half2(e0, e1));
            }
        }
    } else {
        __half* bo = (__half*)sm;            // [64 o][72 l]
        const int vb0 = (oidx - 1) * 64;
        #pragma unroll
        for (int og = 0; og < 8; og++) {
            int ol = og * 8 + 2 * m;
            float b0 = __ldg(&bv[vb0 + ol]), b1 = __ldg(&bv[vb0 + ol + 1]);
            int lg = wid * 16 + g;
            bo[ol * 72 + lg]           = __float2half_rn(C[og][0] + b0);
            bo[(ol + 1) * 72 + lg]     = __float2half_rn(C[og][1] + b1);
            bo[ol * 72 + lg + 8]       = __float2half_rn(C[og][2] + b0);
            bo[(ol + 1) * 72 + lg + 8] = __float2half_rn(C[og][3] + b1);
        }
        __syncthreads();
        const int o = tid >> 1, lh = tid & 1;
        const uint4* src = (const uint4*)(sm + o * 144 + lh * 64);
        uint4* dst = (uint4*)(g_v + (((size_t)(n * CC + vb0 + o)) << 12) + l0 + lh * 32);
        #pragma unroll
        for (int i = 0; i < 4; i++) dst[i] = src[i];
    }
}

// ---------------- kernel 3: BJ=64 mbarrier-skewed fp16 flash attention -------
#define OFF_QH 0            // [64][40] fp16
#define OFF_QL 5120
#define OFF_K  10240        // 2 slots x 10240: [KH 64][40] then [KL 64][40]
#define OFF_V  30720        // 2 slots x 36864: [256][72] fp16
#define OFF_MB 104448       // full[0..1] at +0, empty[0..1] at +16
#define ATTN_SMEM 104704

__device__ __forceinline__ void loadK(uint32_t smb, int n, int j0, int slot, int tid) {
    const uint32_t kbase = smb + OFF_K + slot * 10240;
    #pragma unroll
    for (int it = 0; it < 4; it++) {
        int idx = it * 128 + tid;        // 0..511
        int hl = idx >> 8;
        int r  = (idx >> 2) & 63;
        int s  = idx & 3;
        const __half* src = (hl ? g_kl : g_kh) + ((size_t)((n << 12) + j0 + r)) * 32 + s * 8;
        cp_async16(kbase + hl * 5120 + r * 80 + s * 16, src);
    }
}
__device__ __forceinline__ void loadV(uint32_t smb, int n, int j0, int slot, int tid) {
    const uint32_t vbase = smb + OFF_V + slot * 36864;
    #pragma unroll
    for (int it = 0; it < 16; it++) {
        int idx = it * 128 + tid;        // 0..2047
        int cr = idx >> 3;               // 0..255
        int s  = idx & 7;
        const __half* src = g_v + (((size_t)n * CC + cr) << 12) + j0 + s * 8;
        cp_async16(vbase + cr * 144 + s * 16, src);
    }
}

__global__ __launch_bounds__(128, 2)
void attn_kernel(const float* __restrict__ x,
                 const float* __restrict__ gamma,
                 float* __restrict__ out,
                 int n0) {
    extern __shared__ char sm[];
    const uint32_t smb = smem_u32(sm);
    const int tid  = threadIdx.x;
    const int wid  = tid >> 5, lane = tid & 31;
    const int g    = lane >> 2, m = lane & 3;
    const int iw   = wid * 16;
    const int n    = n0 + blockIdx.y;
    const int i0   = blockIdx.x * BI;

    const uint32_t aoffK = (uint32_t)((lane & 7) * 80 + (lane >> 3) * 16);
    const uint32_t aoffV = (uint32_t)((lane & 7) * 144 + (lane >> 3) * 16);
    const uint32_t mb_full  = smb + OFF_MB;
    const uint32_t mb_empty = smb + OFF_MB + 16;

    if (tid == 0) {
        #pragma unroll
        for (int s = 0; s < 2; s++) {
            MBARRIER_INIT(mb_full + 8 * s, 128);
            MBARRIER_INIT(mb_empty + 8 * s, 4);
        }
    }

    // ---- Q tile via plain ld/st ----
    #pragma unroll
    for (int it = 0; it < 4; it++) {
        int idx  = it * 128 + tid;          // 0..511
        int half = idx >> 8;
        int r    = (idx >> 2) & 63;
        int s    = idx & 3;
        const __half* src = (half ? g_ql : g_qh) + ((size_t)((n << 12) + i0 + r)) * 32 + s * 8;
        uint4 v = *(const uint4*)src;
        *(uint4*)(sm + (half ? OFF_QL : OFF_QH) + r * 80 + s * 16) = v;
    }
    __syncthreads();   // mbarrier init + Q visible

    // ---- prologue: fill slots 0,1 (tiles 0,1) ----
    #pragma unroll
    for (int t = 0; t < 2; t++) {
        loadK(smb, n, t * BJ, t, tid);
        loadV(smb, n, t * BJ, t, tid);
        CP_MBAR_ARRIVE(mb_full + 8 * t);
    }

    // ---- Q fragments ----
    uint32_t qh[2][4], ql[2][4];
    {
        const uint32_t* QHw = (const uint32_t*)(sm + OFF_QH);
        const uint32_t* QLw = (const uint32_t*)(sm + OFF_QL);
        #pragma unroll
        for (int kc = 0; kc < 2; kc++) {
            qh[kc][0] = QHw[(iw + g)     * 20 + 8 * kc + m];
            qh[kc][1] = QHw[(iw + g + 8) * 20 + 8 * kc + m];
            qh[kc][2] = QHw[(iw + g)     * 20 + 8 * kc + 4 + m];
            qh[kc][3] = QHw[(iw + g + 8) * 20 + 8 * kc + 4 + m];
            ql[kc][0] = QLw[(iw + g)     * 20 + 8 * kc + m];
            ql[kc][1] = QLw[(iw + g + 8) * 20 + 8 * kc + m];
            ql[kc][2] = QLw[(iw + g)     * 20 + 8 * kc + 4 + m];
            ql[kc][3] = QLw[(iw + g + 8) * 20 + 8 * kc + 4 + m];
        }
    }

    float O[32][4];
    #pragma unroll
    for (int nt = 0; nt < 32; nt++)
        #pragma unroll
        for (int e = 0; e < 4; e++) O[nt][e] = 0.f;
    float mr0 = -1e30f, mr1 = -1e30f, lr0 = 0.f, lr1 = 0.f;

    for (int jt = 0; jt < NJT; jt++) {
        const int s = jt & 1;

        // ---- per-warp prefetch of tile jt+1 into the other slot ----
        if (jt >= 1 && jt + 1 < NJT) {
            const int t2 = jt + 1;
            const int s2 = t2 & 1;
            MBARRIER_WAIT_PARITY(mb_empty + 8 * s2, (uint32_t)(((t2 >> 1) - 1) & 1));
            loadK(smb, n, t2 * BJ, s2, tid);
            loadV(smb, n, t2 * BJ, s2, tid);
            CP_MBAR_ARRIVE(mb_full + 8 * s2);
        }

        // ---- wait data ----
        MBARRIER_WAIT_PARITY(mb_full + 8 * s, (uint32_t)((jt >> 1) & 1));

        // ---- S = Q K^T (3-term fp16 split), 64 j per tile ----
        const uint32_t kb = smb + OFF_K + s * 10240;
        float C[8][4];
        #pragma unroll
        for (int nt = 0; nt < 8; nt++) {
            C[nt][0] = C[nt][1] = C[nt][2] = C[nt][3] = 0.f;
            uint32_t h0, h1, h2, h3, e0, e1, e2, e3;
            ldsm_x4(h0, h1, h2, h3, kb + nt * 640 + aoffK);
            ldsm_x4(e0, e1, e2, e3, kb + 5120 + nt * 640 + aoffK);
            mma_f16(C[nt], qh[0], h0, h1);  mma_f16(C[nt], ql[0], h0, h1);  mma_f16(C[nt], qh[0], e0, e1);
            mma_f16(C[nt], qh[1], h2, h3);  mma_f16(C[nt], ql[1], h2, h3);  mma_f16(C[nt], qh[1], e2, e3);
        }

        // ---- softmax, exp2 domain ----
        float t0 = -1e30f, t1 = -1e30f;
        #pragma unroll
        for (int nt = 0; nt < 8; nt++) {
            t0 = fmaxf(t0, fmaxf(C[nt][0], C[nt][1]));
            t1 = fmaxf(t1, fmaxf(C[nt][2], C[nt][3]));
        }
        t0 = fmaxf(t0, __shfl_xor_sync(0xffffffffu, t0, 1));
        t0 = fmaxf(t0, __shfl_xor_sync(0xffffffffu, t0, 2));
        t1 = fmaxf(t1, __shfl_xor_sync(0xffffffffu, t1, 1));
        t1 = fmaxf(t1, __shfl_xor_sync(0xffffffffu, t1, 2));
        float mn0 = fmaxf(mr0, t0), mn1 = fmaxf(mr1, t1);
        float al0 = ex2f(mr0 - mn0), al1 = ex2f(mr1 - mn1);
        mr0 = mn0; mr1 = mn1;

        uint32_t P[8][2];
        float rs0 = 0.f, rs1 = 0.f;
        #pragma unroll
        for (int nt = 0; nt < 8; nt++) {
            float p0 = ex2f(C[nt][0] - mn0), p1 = ex2f(C[nt][1] - mn0);
            float p2 = ex2f(C[nt][2] - mn1), p3 = ex2f(C[nt][3] - mn1);
            __half2 h01 = __floats2half2_rn(p0, p1);
            __half2 h23 = __floats2half2_rn(p2, p3);
            P[nt][0] = h2u(h01); P[nt][1] = h2u(h23);
            float2 f01 = __half22float2(h01), f23 = __half22float2(h23);
            rs0 += f01.x + f01.y; rs1 += f23.x + f23.y;
        }
        rs0 += __shfl_xor_sync(0xffffffffu, rs0, 1);
        rs0 += __shfl_xor_sync(0xffffffffu, rs0, 2);
        rs1 += __shfl_xor_sync(0xffffffffu, rs1, 1);
        rs1 += __shfl_xor_sync(0xffffffffu, rs1, 2);
        lr0 = lr0 * al0 + rs0;
        lr1 = lr1 * al1 + rs1;

        if (__any_sync(0xffffffffu, (al0 != 1.f) || (al1 != 1.f))) {
            #pragma unroll
            for (int nt = 0; nt < 32; nt++) {
                O[nt][0] *= al0; O[nt][1] *= al0;
                O[nt][2] *= al1; O[nt][3] *= al1;
            }
        }

        // ---- O += P V  (64 j = 4 k-chunks of 16, f32 accum) ----
        uint32_t pa[4][4];
        #pragma unroll
        for (int kc = 0; kc < 4; kc++) {
            pa[kc][0] = P[2 * kc][0];     pa[kc][1] = P[2 * kc][1];
            pa[kc][2] = P[2 * kc + 1][0]; pa[kc][3] = P[2 * kc + 1][1];
        }
        const uint32_t vb = smb + OFF_V + s * 36864;
        #pragma unroll
        for (int nt = 0; nt < 32; nt++) {
            uint32_t b00, b01, b10, b11, c00, c01, c10, c11;
            ldsm_x4(b00, b01, b10, b11, vb + nt * 1152 + aoffV);
            ldsm_x4(c00, c01, c10, c11, vb + nt * 1152 + 64 + aoffV);
            mma_f16(O[nt], pa[0], b00, b01);
            mma_f16(O[nt], pa[1], b10, b11);
            mma_f16(O[nt], pa[2], c00, c01);
            mma_f16(O[nt], pa[3], c10, c11);
        }

        // ---- this warp done reading slot s ----
        __syncwarp();
        if (lane == 0) MBAR_ARRIVE(mb_empty + 8 * s);
    }

    // ---- epilogue ----
    const float linv0 = 1.0f / lr0;
    const float linv1 = 1.0f / lr1;
    const float gam = __ldg(gamma);
    #pragma unroll
    for (int nt = 0; nt < 32; nt++) {
        #pragma unroll
        for (int e = 0; e < 4; e++) {
            int c   = 8 * nt + 2 * m + (e & 1);
            int row = iw + g + 8 * (e >> 1);
            size_t idx = (((size_t)(n * CC + c)) << 12) + i0 + row;
            float o = O[nt][e] * ((e >> 1) ? linv1 : linv0);
            out[idx] = gam * o + __ldg(&x[idx]);
        }
    }
}

// ---------------- launch: two-stream batch-split pipeline --------------------
extern "C" void kernel_launch(void* const* d_in, const int* in_sizes, int n_in,
                              void* d_out, int out_size) {
    const float* x     = (const float*)d_in[0];
    const float* Wq    = (const float*)d_in[1];
    const float* bq    = (const float*)d_in[2];
    const float* Wk    = (const float*)d_in[3];
    const float* bk    = (const float*)d_in[4];
    const float* Wv    = (const float*)d_in[5];
    const float* bv    = (const float*)d_in[6];
    const float* gamma = (const float*)d_in[7];
    float* out = (float*)d_out;

    cudaFuncSetAttribute(proj_kernel, cudaFuncAttributeMaxDynamicSharedMemorySize, PROJ_SMEM);
    cudaFuncSetAttribute(attn_kernel, cudaFuncAttributeMaxDynamicSharedMemorySize, ATTN_SMEM);

    cudaStream_t s2;
    cudaEvent_t ev0, ev2;
    cudaStreamCreateWithFlags(&s2, cudaStreamNonBlocking);
    cudaEventCreateWithFlags(&ev0, cudaEventDisableTiming);
    cudaEventCreateWithFlags(&ev2, cudaEventDisableTiming);

    const int HB = NB / 2;   // 4 batches per half

    // main (legacy) stream: wtrans -> fork -> half A
    wtrans_kernel<<<320, 256>>>(Wq, Wk, Wv);
    cudaEventRecord(ev0, 0);

    // branch B on s2
    cudaStreamWaitEvent(s2, ev0, 0);
    proj_kernel<<<dim3(LL / 64, 5, HB), 128, PROJ_SMEM, s2>>>(x, bq, bk, bv, HB);
    attn_kernel<<<dim3(LL / BI, HB), 128, ATTN_SMEM, s2>>>(x, gamma, out, HB);
    cudaEventRecord(ev2, s2);

    // branch A on main stream
    proj_kernel<<<dim3(LL / 64, 5, HB), 128, PROJ_SMEM>>>(x, bq, bk, bv, 0);
    attn_kernel<<<dim3(LL / BI, HB), 128, ATTN_SMEM>>>(x, gamma, out, 0);

    // join
    cudaStreamWaitEvent(0, ev2, 0);

    cudaEventDestroy(ev0);
    cudaEventDestroy(ev2);
    cudaStreamDestroy(s2);
}

// round 15
// speedup vs baseline: 1.3265x; 1.0440x over previous
#include <cuda_runtime.h>
#include <cuda_fp16.h>
#include <cstdint>

#define NB   8
#define CC   256
#define CQK  32
#define LL   4096
#define BI   64
#define BJ   64
#define NJT  (LL / BJ)          // 64 j-tiles
#define INVLN2 1.4426950408889634f

// ---------------- scratch (device globals) ----------------------------------
__device__ __half g_Wh [320 * 256];                 // fused weights fp16-hi, (o, c)
__device__ __half g_Wql[64 * 256];                  // fp16-lo residual, q/k rows only
__device__ __half g_qh [NB * LL * CQK];             // (N, L, 32) token-major fp16-hi
__device__ __half g_ql [NB * LL * CQK];
__device__ __half g_kh [NB * LL * CQK];             // (N, L, 32) fp16-hi (scaled 1/ln2)
__device__ __half g_kl [NB * LL * CQK];
__device__ __half g_v  [(size_t)NB * CC * LL];      // (N, C, L) fp16, l contiguous

// ---------------- helpers ----------------------------------------------------
__device__ __forceinline__ uint32_t smem_u32(const void* p) {
    uint32_t a;
    asm("{ .reg .u64 t; cvta.to.shared.u64 t, %1; cvt.u32.u64 %0, t; }" : "=r"(a) : "l"(p));
    return a;
}
__device__ __forceinline__ void cp_async16(uint32_t dst, const void* src) {
    asm volatile("cp.async.cg.shared.global [%0], [%1], 16;"
                 :: "r"(dst), "l"((unsigned long long)__cvta_generic_to_global(src)) : "memory");
}
#define CP_COMMIT() asm volatile("cp.async.commit_group;" ::: "memory")
#define CP_WAIT0()  asm volatile("cp.async.wait_group 0;" ::: "memory")
#define CP_WAIT1()  asm volatile("cp.async.wait_group 1;" ::: "memory")

// mbarrier (sm_80+/sm_90 baseline PTX; no arch-'a' features)
#define MBARRIER_INIT(mbar, cnt) \
    asm volatile("mbarrier.init.shared.b64 [%0], %1;" :: "r"((uint32_t)(mbar)), "r"((uint32_t)(cnt)) : "memory")
#define MBAR_ARRIVE(mbar) \
    asm volatile("mbarrier.arrive.shared::cta.b64 _, [%0];" :: "r"((uint32_t)(mbar)) : "memory")
// NOTE: .noinc is load-bearing (default form pre-increments -> deadlock).
#define CP_MBAR_ARRIVE(mbar) \
    asm volatile("cp.async.mbarrier.arrive.noinc.shared::cta.b64 [%0];" :: "r"((uint32_t)(mbar)) : "memory")
#define MBARRIER_WAIT_PARITY(mbar, parity) do { \
    uint32_t _m = (uint32_t)(mbar); uint32_t _p = (uint32_t)(parity); uint32_t _d; \
    asm volatile("{\n\t.reg .pred p;\n\t" \
        "mbarrier.try_wait.parity.acquire.cta.shared::cta.b64 p, [%1], %2;\n\t" \
        "selp.b32 %0, 1, 0, p;\n\t}" : "=r"(_d) : "r"(_m), "r"(_p) : "memory"); \
    if (!_d) { \
        asm volatile("{\n\t.reg .pred P1;\n\t" \
            "WAIT_LOOP_%=:\n\t" \
            "mbarrier.try_wait.parity.acquire.cta.shared::cta.b64 P1, [%0], %1, 0x989680;\n\t" \
            "@P1 bra.uni WAIT_DONE_%=;\n\t" \
            "bra.uni WAIT_LOOP_%=;\n\t" \
            "WAIT_DONE_%=:\n\t}" :: "r"(_m), "r"(_p) : "memory"); \
    } \
} while (0)

__device__ __forceinline__ uint32_t h2u(__half2 h) { return *reinterpret_cast<uint32_t*>(&h); }
__device__ __forceinline__ float ex2f(float x) {
    float r;
    asm("ex2.approx.f32 %0, %1;" : "=f"(r) : "f"(x));
    return r;
}
__device__ __forceinline__ void ldsm_x4(uint32_t& r0, uint32_t& r1, uint32_t& r2, uint32_t& r3,
                                        uint32_t addr) {
    asm volatile("ldmatrix.sync.aligned.m8n8.x4.shared.b16 {%0,%1,%2,%3}, [%4];"
                 : "=r"(r0), "=r"(r1), "=r"(r2), "=r"(r3) : "r"(addr));
}
__device__ __forceinline__ void ldsm_x4a(uint32_t r[4], uint32_t addr) {
    ldsm_x4(r[0], r[1], r[2], r[3], addr);
}
__device__ __forceinline__ void mma_f16(float c[4], const uint32_t a[4],
                                        uint32_t b0, uint32_t b1) {
    asm("mma.sync.aligned.m16n8k16.row.col.f32.f16.f16.f32 "
        "{%0,%1,%2,%3}, {%4,%5,%6,%7}, {%8,%9}, {%0,%1,%2,%3};"
        : "+f"(c[0]), "+f"(c[1]), "+f"(c[2]), "+f"(c[3])
        : "r"(a[0]), "r"(a[1]), "r"(a[2]), "r"(a[3]), "r"(b0), "r"(b1));
}

// ---------------- kernel 1: weight prep (fp16 hi + q/k lo residual) ----------
__global__ void wtrans_kernel(const float* __restrict__ Wq,
                              const float* __restrict__ Wk,
                              const float* __restrict__ Wv) {
    int idx = blockIdx.x * 256 + threadIdx.x;
    if (idx >= 320 * 256) return;
    int o = idx >> 8, c = idx & 255;
    float v;
    if (o < 32)       v = Wq[o * 256 + c];
    else if (o < 64)  v = Wk[(o - 32) * 256 + c];
    else              v = Wv[(o - 64) * 256 + c];
    __half h = __float2half_rn(v);
    g_Wh[o * 256 + c] = h;
    if (o < 64) g_Wql[o * 256 + c] = __float2half_rn(v - __half2float(h));
}

// ---------------- kernel 2: tensor-core fused QKV projection ------------------
// 256 threads / 8 warps: wg = wid>>2 picks output half (4 og each),
// wblk = wid&3 picks the 16-row l-block. 2 CTA/SM -> 16 warps/SM.
#define PJ_XH 0
#define PJ_XL 33792
#define PJ_WH 67584        // 3 slots x 5120
#define PJ_WL 82944        // 3 slots x 5120 (q/k CTAs only)
#define PROJ_SMEM 98304

__global__ __launch_bounds__(256, 2)
void proj_kernel(const float* __restrict__ x,
                 const float* __restrict__ bq,
                 const float* __restrict__ bk,
                 const float* __restrict__ bv,
                 int n0) {
    extern __shared__ char sm[];
    const uint32_t smb = smem_u32(sm);
    const int tid = threadIdx.x;
    const int wid = tid >> 5, lane = tid & 31;
    const int g = lane >> 2, m = lane & 3;
    const int wg = wid >> 2, wblk = wid & 3;
    const int n = n0 + blockIdx.z;
    const int oidx = blockIdx.y;
    const int l0 = blockIdx.x * 64;
    const int obase = oidx * 64;
    const bool qk = (oidx == 0);

    auto issueW = [&](int r, int slot) {
        int row = tid >> 2, seg = tid & 3;     // 256 threads -> one 16B seg each
        cp_async16(smb + PJ_WH + slot * 5120 + row * 80 + seg * 16,
                   g_Wh + (obase + row) * 256 + r * 32 + seg * 8);
        if (qk)
            cp_async16(smb + PJ_WL + slot * 5120 + row * 80 + seg * 16,
                       g_Wql + row * 256 + r * 32 + seg * 8);
        CP_COMMIT();
    };
    issueW(0, 0);
    issueW(1, 1);

    // ---- convert + transpose x tile: f32 (c,l) -> fp16 hi/lo [l][264] -------
    {
        const float* xb = x + ((size_t)n << 20) + l0;
        const int l = tid & 63, p0 = tid >> 6;     // p0 in 0..3
        #pragma unroll 4
        for (int i = 0; i < 32; i++) {
            int p = p0 + 4 * i;                    // c-pair index 0..127
            int c = 2 * p;
            float f0 = __ldg(&xb[(size_t)c * 4096 + l]);
            float f1 = __ldg(&xb[(size_t)(c + 1) * 4096 + l]);
            __half h0 = __float2half_rn(f0), h1 = __float2half_rn(f1);
            __half e0 = __float2half_rn(f0 - __half2float(h0));
            __half e1 = __float2half_rn(f1 - __half2float(h1));
            *(uint32_t*)(sm + PJ_XH + l * 528 + p * 4) = h2u(__halves2half2(h0, h1));
            *(uint32_t*)(sm + PJ_XL + l * 528 + p * 4) = h2u(__halves2half2(e0, e1));
        }
    }

    float C[4][4];
    #pragma unroll
    for (int og = 0; og < 4; og++)
        #pragma unroll
        for (int e = 0; e < 4; e++) C[og][e] = 0.f;

    const uint32_t aoffA = (uint32_t)((lane & 15) * 528 + (lane >> 4) * 16);
    const uint32_t aoffB = (uint32_t)((lane & 7) * 80 + (lane >> 3) * 16);
    const uint32_t abase = smb + (uint32_t)(wblk * 16) * 528;

    for (int r = 0; r < 8; r++) {
        const int slot = r % 3;
        if (r == 7) { CP_WAIT0(); } else { CP_WAIT1(); }
        __syncthreads();
        if (r + 2 < 8) issueW(r + 2, (r + 2) % 3);

        uint32_t axh0[4], axh1[4], axl0[4], axl1[4];
        ldsm_x4a(axh0, abase + PJ_XH + r * 64 + aoffA);
        ldsm_x4a(axh1, abase + PJ_XH + r * 64 + 32 + aoffA);
        ldsm_x4a(axl0, abase + PJ_XL + r * 64 + aoffA);
        ldsm_x4a(axl1, abase + PJ_XL + r * 64 + 32 + aoffA);

        const uint32_t wb  = smb + PJ_WH + slot * 5120;
        const uint32_t wlb = smb + PJ_WL + slot * 5120;
        #pragma unroll
        for (int ogl = 0; ogl < 4; ogl++) {
            const int og = wg * 4 + ogl;
            uint32_t b0, b1, b2, b3;
            ldsm_x4(b0, b1, b2, b3, wb + og * 640 + aoffB);
            mma_f16(C[ogl], axh0, b0, b1);
            mma_f16(C[ogl], axl0, b0, b1);
            mma_f16(C[ogl], axh1, b2, b3);
            mma_f16(C[ogl], axl1, b2, b3);
            if (qk) {
                uint32_t c0, c1, c2, c3;
                ldsm_x4(c0, c1, c2, c3, wlb + og * 640 + aoffB);
                mma_f16(C[ogl], axh0, c0, c1);
                mma_f16(C[ogl], axh1, c2, c3);
            }
        }
    }
    __syncthreads();

    if (qk) {
        #pragma unroll
        for (int ogl = 0; ogl < 4; ogl++) {
            const int og = wg * 4 + ogl;
            int ol = og * 8 + 2 * m;
            bool isq = (ol < 32);
            float sc = isq ? 1.0f : INVLN2;
            const float* bias = isq ? bq : bk;
            int bo = isq ? ol : ol - 32;
            float b0 = __ldg(&bias[bo]), b1 = __ldg(&bias[bo + 1]);
            uint32_t* dsth = (uint32_t*)(isq ? g_qh : g_kh);
            uint32_t* dstl = (uint32_t*)(isq ? g_ql : g_kl);
            int col = (isq ? og * 4 : (og - 4) * 4) + m;
            #pragma unroll
            for (int rr = 0; rr < 2; rr++) {
                float f0 = (C[ogl][2 * rr]     + b0) * sc;
                float f1 = (C[ogl][2 * rr + 1] + b1) * sc;
                __half h0 = __float2half_rn(f0), h1 = __float2half_rn(f1);
                __half e0 = __float2half_rn(f0 - __half2float(h0));
                __half e1 = __float2half_rn(f1 - __half2float(h1));
                size_t lg = (size_t)(n << 12) + l0 + wblk * 16 + g + 8 * rr;
                dsth[lg * 16 + col] = h2u(__halves2half2(h0, h1));
                dstl[lg * 16 + col] = h2u(__halves2half2(e0, e1));
            }
        }
    } else {
        __half* bo = (__half*)sm;            // [64 o][72 l]
        const int vb0 = (oidx - 1) * 64;
        #pragma unroll
        for (int ogl = 0; ogl < 4; ogl++) {
            const int og = wg * 4 + ogl;
            int ol = og * 8 + 2 * m;
            float b0 = __ldg(&bv[vb0 + ol]), b1 = __ldg(&bv[vb0 + ol + 1]);
            int lg = wblk * 16 + g;
            bo[ol * 72 + lg]           = __float2half_rn(C[ogl][0] + b0);
            bo[(ol + 1) * 72 + lg]     = __float2half_rn(C[ogl][1] + b1);
            bo[ol * 72 + lg + 8]       = __float2half_rn(C[ogl][2] + b0);
            bo[(ol + 1) * 72 + lg + 8] = __float2half_rn(C[ogl][3] + b1);
        }
        __syncthreads();
        const int o = tid >> 2, q = tid & 3;
        const uint4* src = (const uint4*)(sm + o * 144 + q * 32);
        uint4* dst = (uint4*)(g_v + (((size_t)(n * CC + vb0 + o)) << 12) + l0 + q * 16);
        dst[0] = src[0];
        dst[1] = src[1];
    }
}

// ---------------- kernel 3: BJ=64 mbarrier-skewed fp16 flash attention -------
#define OFF_QH 0            // [64][40] fp16
#define OFF_QL 5120
#define OFF_K  10240        // 2 slots x 10240: [KH 64][40] then [KL 64][40]
#define OFF_V  30720        // 2 slots x 36864: [256][72] fp16
#define OFF_MB 104448       // full[0..1] at +0, empty[0..1] at +16
#define ATTN_SMEM 104704

__device__ __forceinline__ void loadK(uint32_t smb, int n, int j0, int slot, int tid) {
    const uint32_t kbase = smb + OFF_K + slot * 10240;
    #pragma unroll
    for (int it = 0; it < 4; it++) {
        int idx = it * 128 + tid;        // 0..511
        int hl = idx >> 8;
        int r  = (idx >> 2) & 63;
        int s  = idx & 3;
        const __half* src = (hl ? g_kl : g_kh) + ((size_t)((n << 12) + j0 + r)) * 32 + s * 8;
        cp_async16(kbase + hl * 5120 + r * 80 + s * 16, src);
    }
}
__device__ __forceinline__ void loadV(uint32_t smb, int n, int j0, int slot, int tid) {
    const uint32_t vbase = smb + OFF_V + slot * 36864;
    #pragma unroll
    for (int it = 0; it < 16; it++) {
        int idx = it * 128 + tid;        // 0..2047
        int cr = idx >> 3;               // 0..255
        int s  = idx & 7;
        const __half* src = g_v + (((size_t)n * CC + cr) << 12) + j0 + s * 8;
        cp_async16(vbase + cr * 144 + s * 16, src);
    }
}

__global__ __launch_bounds__(128, 2)
void attn_kernel(const float* __restrict__ x,
                 const float* __restrict__ gamma,
                 float* __restrict__ out,
                 int n0) {
    extern __shared__ char sm[];
    const uint32_t smb = smem_u32(sm);
    const int tid  = threadIdx.x;
    const int wid  = tid >> 5, lane = tid & 31;
    const int g    = lane >> 2, m = lane & 3;
    const int iw   = wid * 16;
    const int n    = n0 + blockIdx.y;
    const int i0   = blockIdx.x * BI;

    const uint32_t aoffK = (uint32_t)((lane & 7) * 80 + (lane >> 3) * 16);
    const uint32_t aoffV = (uint32_t)((lane & 7) * 144 + (lane >> 3) * 16);
    const uint32_t mb_full  = smb + OFF_MB;
    const uint32_t mb_empty = smb + OFF_MB + 16;

    if (tid == 0) {
        #pragma unroll
        for (int s = 0; s < 2; s++) {
            MBARRIER_INIT(mb_full + 8 * s, 128);
            MBARRIER_INIT(mb_empty + 8 * s, 4);
        }
    }

    // ---- Q tile via plain ld/st ----
    #pragma unroll
    for (int it = 0; it < 4; it++) {
        int idx  = it * 128 + tid;          // 0..511
        int half = idx >> 8;
        int r    = (idx >> 2) & 63;
        int s    = idx & 3;
        const __half* src = (half ? g_ql : g_qh) + ((size_t)((n << 12) + i0 + r)) * 32 + s * 8;
        uint4 v = *(const uint4*)src;
        *(uint4*)(sm + (half ? OFF_QL : OFF_QH) + r * 80 + s * 16) = v;
    }
    __syncthreads();   // mbarrier init + Q visible

    // ---- prologue: fill slots 0,1 (tiles 0,1) ----
    #pragma unroll
    for (int t = 0; t < 2; t++) {
        loadK(smb, n, t * BJ, t, tid);
        loadV(smb, n, t * BJ, t, tid);
        CP_MBAR_ARRIVE(mb_full + 8 * t);
    }

    // ---- Q fragments ----
    uint32_t qh[2][4], ql[2][4];
    {
        const uint32_t* QHw = (const uint32_t*)(sm + OFF_QH);
        const uint32_t* QLw = (const uint32_t*)(sm + OFF_QL);
        #pragma unroll
        for (int kc = 0; kc < 2; kc++) {
            qh[kc][0] = QHw[(iw + g)     * 20 + 8 * kc + m];
            qh[kc][1] = QHw[(iw + g + 8) * 20 + 8 * kc + m];
            qh[kc][2] = QHw[(iw + g)     * 20 + 8 * kc + 4 + m];
            qh[kc][3] = QHw[(iw + g + 8) * 20 + 8 * kc + 4 + m];
            ql[kc][0] = QLw[(iw + g)     * 20 + 8 * kc + m];
            ql[kc][1] = QLw[(iw + g + 8) * 20 + 8 * kc + m];
            ql[kc][2] = QLw[(iw + g)     * 20 + 8 * kc + 4 + m];
            ql[kc][3] = QLw[(iw + g + 8) * 20 + 8 * kc + 4 + m];
        }
    }

    float O[32][4];
    #pragma unroll
    for (int nt = 0; nt < 32; nt++)
        #pragma unroll
        for (int e = 0; e < 4; e++) O[nt][e] = 0.f;
    float mr0 = -1e30f, mr1 = -1e30f, lr0 = 0.f, lr1 = 0.f;

    for (int jt = 0; jt < NJT; jt++) {
        const int s = jt & 1;

        // ---- per-warp prefetch of tile jt+1 into the other slot ----
        if (jt >= 1 && jt + 1 < NJT) {
            const int t2 = jt + 1;
            const int s2 = t2 & 1;
            MBARRIER_WAIT_PARITY(mb_empty + 8 * s2, (uint32_t)(((t2 >> 1) - 1) & 1));
            loadK(smb, n, t2 * BJ, s2, tid);
            loadV(smb, n, t2 * BJ, s2, tid);
            CP_MBAR_ARRIVE(mb_full + 8 * s2);
        }

        // ---- wait data ----
        MBARRIER_WAIT_PARITY(mb_full + 8 * s, (uint32_t)((jt >> 1) & 1));

        // ---- S = Q K^T (3-term fp16 split), 64 j per tile ----
        const uint32_t kb = smb + OFF_K + s * 10240;
        float C[8][4];
        #pragma unroll
        for (int nt = 0; nt < 8; nt++) {
            C[nt][0] = C[nt][1] = C[nt][2] = C[nt][3] = 0.f;
            uint32_t h0, h1, h2, h3, e0, e1, e2, e3;
            ldsm_x4(h0, h1, h2, h3, kb + nt * 640 + aoffK);
            ldsm_x4(e0, e1, e2, e3, kb + 5120 + nt * 640 + aoffK);
            mma_f16(C[nt], qh[0], h0, h1);  mma_f16(C[nt], ql[0], h0, h1);  mma_f16(C[nt], qh[0], e0, e1);
            mma_f16(C[nt], qh[1], h2, h3);  mma_f16(C[nt], ql[1], h2, h3);  mma_f16(C[nt], qh[1], e2, e3);
        }

        // ---- softmax, exp2 domain ----
        float t0 = -1e30f, t1 = -1e30f;
        #pragma unroll
        for (int nt = 0; nt < 8; nt++) {
            t0 = fmaxf(t0, fmaxf(C[nt][0], C[nt][1]));
            t1 = fmaxf(t1, fmaxf(C[nt][2], C[nt][3]));
        }
        t0 = fmaxf(t0, __shfl_xor_sync(0xffffffffu, t0, 1));
        t0 = fmaxf(t0, __shfl_xor_sync(0xffffffffu, t0, 2));
        t1 = fmaxf(t1, __shfl_xor_sync(0xffffffffu, t1, 1));
        t1 = fmaxf(t1, __shfl_xor_sync(0xffffffffu, t1, 2));
        float mn0 = fmaxf(mr0, t0), mn1 = fmaxf(mr1, t1);
        float al0 = ex2f(mr0 - mn0), al1 = ex2f(mr1 - mn1);
        mr0 = mn0; mr1 = mn1;

        uint32_t P[8][2];
        float rs0 = 0.f, rs1 = 0.f;
        #pragma unroll
        for (int nt = 0; nt < 8; nt++) {
            float p0 = ex2f(C[nt][0] - mn0), p1 = ex2f(C[nt][1] - mn0);
            float p2 = ex2f(C[nt][2] - mn1), p3 = ex2f(C[nt][3] - mn1);
            __half2 h01 = __floats2half2_rn(p0, p1);
            __half2 h23 = __floats2half2_rn(p2, p3);
            P[nt][0] = h2u(h01); P[nt][1] = h2u(h23);
            float2 f01 = __half22float2(h01), f23 = __half22float2(h23);
            rs0 += f01.x + f01.y; rs1 += f23.x + f23.y;
        }
        rs0 += __shfl_xor_sync(0xffffffffu, rs0, 1);
        rs0 += __shfl_xor_sync(0xffffffffu, rs0, 2);
        rs1 += __shfl_xor_sync(0xffffffffu, rs1, 1);
        rs1 += __shfl_xor_sync(0xffffffffu, rs1, 2);
        lr0 = lr0 * al0 + rs0;
        lr1 = lr1 * al1 + rs1;

        if (__any_sync(0xffffffffu, (al0 != 1.f) || (al1 != 1.f))) {
            #pragma unroll
            for (int nt = 0; nt < 32; nt++) {
                O[nt][0] *= al0; O[nt][1] *= al0;
                O[nt][2] *= al1; O[nt][3] *= al1;
            }
        }

        // ---- O += P V  (64 j = 4 k-chunks of 16, f32 accum) ----
        uint32_t pa[4][4];
        #pragma unroll
        for (int kc = 0; kc < 4; kc++) {
            pa[kc][0] = P[2 * kc][0];     pa[kc][1] = P[2 * kc][1];
            pa[kc][2] = P[2 * kc + 1][0]; pa[kc][3] = P[2 * kc + 1][1];
        }
        const uint32_t vb = smb + OFF_V + s * 36864;
        #pragma unroll
        for (int nt = 0; nt < 32; nt++) {
            uint32_t b00, b01, b10, b11, c00, c01, c10, c11;
            ldsm_x4(b00, b01, b10, b11, vb + nt * 1152 + aoffV);
            ldsm_x4(c00, c01, c10, c11, vb + nt * 1152 + 64 + aoffV);
            mma_f16(O[nt], pa[0], b00, b01);
            mma_f16(O[nt], pa[1], b10, b11);
            mma_f16(O[nt], pa[2], c00, c01);
            mma_f16(O[nt], pa[3], c10, c11);
        }

        // ---- this warp done reading slot s ----
        __syncwarp();
        if (lane == 0) MBAR_ARRIVE(mb_empty + 8 * s);
    }

    // ---- epilogue ----
    const float linv0 = 1.0f / lr0;
    const float linv1 = 1.0f / lr1;
    const float gam = __ldg(gamma);
    #pragma unroll
    for (int nt = 0; nt < 32; nt++) {
        #pragma unroll
        for (int e = 0; e < 4; e++) {
            int c   = 8 * nt + 2 * m + (e & 1);
            int row = iw + g + 8 * (e >> 1);
            size_t idx = (((size_t)(n * CC + c)) << 12) + i0 + row;
            float o = O[nt][e] * ((e >> 1) ? linv1 : linv0);
            out[idx] = gam * o + __ldg(&x[idx]);
        }
    }
}

// ---------------- launch: two-stream batch-split pipeline --------------------
extern "C" void kernel_launch(void* const* d_in, const int* in_sizes, int n_in,
                              void* d_out, int out_size) {
    const float* x     = (const float*)d_in[0];
    const float* Wq    = (const float*)d_in[1];
    const float* bq    = (const float*)d_in[2];
    const float* Wk    = (const float*)d_in[3];
    const float* bk    = (const float*)d_in[4];
    const float* Wv    = (const float*)d_in[5];
    const float* bv    = (const float*)d_in[6];
    const float* gamma = (const float*)d_in[7];
    float* out = (float*)d_out;

    cudaFuncSetAttribute(proj_kernel, cudaFuncAttributeMaxDynamicSharedMemorySize, PROJ_SMEM);
    cudaFuncSetAttribute(attn_kernel, cudaFuncAttributeMaxDynamicSharedMemorySize, ATTN_SMEM);

    cudaStream_t s2;
    cudaEvent_t ev0, ev2;
    cudaStreamCreateWithFlags(&s2, cudaStreamNonBlocking);
    cudaEventCreateWithFlags(&ev0, cudaEventDisableTiming);
    cudaEventCreateWithFlags(&ev2, cudaEventDisableTiming);

    const int HB = NB / 2;   // 4 batches per half

    // main (legacy) stream: wtrans -> fork -> half A
    wtrans_kernel<<<320, 256>>>(Wq, Wk, Wv);
    cudaEventRecord(ev0, 0);

    // branch B on s2
    cudaStreamWaitEvent(s2, ev0, 0);
    proj_kernel<<<dim3(LL / 64, 5, HB), 256, PROJ_SMEM, s2>>>(x, bq, bk, bv, HB);
    attn_kernel<<<dim3(LL / BI, HB), 128, ATTN_SMEM, s2>>>(x, gamma, out, HB);
    cudaEventRecord(ev2, s2);

    // branch A on main stream
    proj_kernel<<<dim3(LL / 64, 5, HB), 256, PROJ_SMEM>>>(x, bq, bk, bv, 0);
    attn_kernel<<<dim3(LL / BI, HB), 128, ATTN_SMEM>>>(x, gamma, out, 0);

    // join
    cudaStreamWaitEvent(0, ev2, 0);

    cudaEventDestroy(ev0);
    cudaEventDestroy(ev2);
    cudaStreamDestroy(s2);
}

// round 16
// speedup vs baseline: 1.4514x; 1.0941x over previous
#include <cuda_runtime.h>
#include <cuda_fp16.h>
#include <cstdint>

#define NB   8
#define CC   256
#define CQK  32
#define LL   4096
#define BI   64
#define BJ   64
#define NJT  (LL / BJ)          // 64 j-tiles
#define INVLN2 1.4426950408889634f

// ---------------- scratch (device globals) ----------------------------------
__device__ __half g_Wh [320 * 256];                 // fused weights fp16-hi, (o, c)
__device__ __half g_Wql[64 * 256];                  // fp16-lo residual, q/k rows only
__device__ __half g_qh [NB * LL * CQK];             // (N, L, 32) token-major fp16-hi
__device__ __half g_ql [NB * LL * CQK];
__device__ __half g_kh [NB * LL * CQK];             // (N, L, 32) fp16 (scaled 1/ln2); no residual
__device__ __half g_v  [(size_t)NB * CC * LL];      // (N, C, L) fp16, l contiguous

// ---------------- helpers ----------------------------------------------------
__device__ __forceinline__ uint32_t smem_u32(const void* p) {
    uint32_t a;
    asm("{ .reg .u64 t; cvta.to.shared.u64 t, %1; cvt.u32.u64 %0, t; }" : "=r"(a) : "l"(p));
    return a;
}
__device__ __forceinline__ void cp_async16(uint32_t dst, const void* src) {
    asm volatile("cp.async.cg.shared.global [%0], [%1], 16;"
                 :: "r"(dst), "l"((unsigned long long)__cvta_generic_to_global(src)) : "memory");
}
#define CP_COMMIT() asm volatile("cp.async.commit_group;" ::: "memory")
#define CP_WAIT0()  asm volatile("cp.async.wait_group 0;" ::: "memory")
#define CP_WAIT1()  asm volatile("cp.async.wait_group 1;" ::: "memory")

// mbarrier (sm_80+/sm_90 baseline PTX; no arch-'a' features)
#define MBARRIER_INIT(mbar, cnt) \
    asm volatile("mbarrier.init.shared.b64 [%0], %1;" :: "r"((uint32_t)(mbar)), "r"((uint32_t)(cnt)) : "memory")
#define MBAR_ARRIVE(mbar) \
    asm volatile("mbarrier.arrive.shared::cta.b64 _, [%0];" :: "r"((uint32_t)(mbar)) : "memory")
// NOTE: .noinc is load-bearing (default form pre-increments -> deadlock).
#define CP_MBAR_ARRIVE(mbar) \
    asm volatile("cp.async.mbarrier.arrive.noinc.shared::cta.b64 [%0];" :: "r"((uint32_t)(mbar)) : "memory")
#define MBARRIER_WAIT_PARITY(mbar, parity) do { \
    uint32_t _m = (uint32_t)(mbar); uint32_t _p = (uint32_t)(parity); uint32_t _d; \
    asm volatile("{\n\t.reg .pred p;\n\t" \
        "mbarrier.try_wait.parity.acquire.cta.shared::cta.b64 p, [%1], %2;\n\t" \
        "selp.b32 %0, 1, 0, p;\n\t}" : "=r"(_d) : "r"(_m), "r"(_p) : "memory"); \
    if (!_d) { \
        asm volatile("{\n\t.reg .pred P1;\n\t" \
            "WAIT_LOOP_%=:\n\t" \
            "mbarrier.try_wait.parity.acquire.cta.shared::cta.b64 P1, [%0], %1, 0x989680;\n\t" \
            "@P1 bra.uni WAIT_DONE_%=;\n\t" \
            "bra.uni WAIT_LOOP_%=;\n\t" \
            "WAIT_DONE_%=:\n\t}" :: "r"(_m), "r"(_p) : "memory"); \
    } \
} while (0)

__device__ __forceinline__ uint32_t h2u(__half2 h) { return *reinterpret_cast<uint32_t*>(&h); }
__device__ __forceinline__ float ex2f(float x) {
    float r;
    asm("ex2.approx.f32 %0, %1;" : "=f"(r) : "f"(x));
    return r;
}
__device__ __forceinline__ void ldsm_x4(uint32_t& r0, uint32_t& r1, uint32_t& r2, uint32_t& r3,
                                        uint32_t addr) {
    asm volatile("ldmatrix.sync.aligned.m8n8.x4.shared.b16 {%0,%1,%2,%3}, [%4];"
                 : "=r"(r0), "=r"(r1), "=r"(r2), "=r"(r3) : "r"(addr));
}
__device__ __forceinline__ void ldsm_x4a(uint32_t r[4], uint32_t addr) {
    ldsm_x4(r[0], r[1], r[2], r[3], addr);
}
__device__ __forceinline__ void mma_f16(float c[4], const uint32_t a[4],
                                        uint32_t b0, uint32_t b1) {
    asm("mma.sync.aligned.m16n8k16.row.col.f32.f16.f16.f32 "
        "{%0,%1,%2,%3}, {%4,%5,%6,%7}, {%8,%9}, {%0,%1,%2,%3};"
        : "+f"(c[0]), "+f"(c[1]), "+f"(c[2]), "+f"(c[3])
        : "r"(a[0]), "r"(a[1]), "r"(a[2]), "r"(a[3]), "r"(b0), "r"(b1));
}

// ---------------- kernel 1: weight prep (fp16 hi + q/k lo residual) ----------
__global__ void wtrans_kernel(const float* __restrict__ Wq,
                              const float* __restrict__ Wk,
                              const float* __restrict__ Wv) {
    int idx = blockIdx.x * 256 + threadIdx.x;
    if (idx >= 320 * 256) return;
    int o = idx >> 8, c = idx & 255;
    float v;
    if (o < 32)       v = Wq[o * 256 + c];
    else if (o < 64)  v = Wk[(o - 32) * 256 + c];
    else              v = Wv[(o - 64) * 256 + c];
    __half h = __float2half_rn(v);
    g_Wh[o * 256 + c] = h;
    if (o < 64) g_Wql[o * 256 + c] = __float2half_rn(v - __half2float(h));
}

// ---------------- kernel 2: tensor-core fused QKV projection ------------------
// 256 threads / 8 warps: wg = wid>>2 picks output half (4 og each),
// wblk = wid&3 picks the 16-row l-block. 2 CTA/SM -> 16 warps/SM.
#define PJ_XH 0
#define PJ_XL 33792
#define PJ_WH 67584        // 3 slots x 5120
#define PJ_WL 82944        // 3 slots x 5120 (q/k CTAs only)
#define PROJ_SMEM 98304

__global__ __launch_bounds__(256, 2)
void proj_kernel(const float* __restrict__ x,
                 const float* __restrict__ bq,
                 const float* __restrict__ bk,
                 const float* __restrict__ bv,
                 int n0) {
    extern __shared__ char sm[];
    const uint32_t smb = smem_u32(sm);
    const int tid = threadIdx.x;
    const int wid = tid >> 5, lane = tid & 31;
    const int g = lane >> 2, m = lane & 3;
    const int wg = wid >> 2, wblk = wid & 3;
    const int n = n0 + blockIdx.z;
    const int oidx = blockIdx.y;
    const int l0 = blockIdx.x * 64;
    const int obase = oidx * 64;
    const bool qk = (oidx == 0);

    auto issueW = [&](int r, int slot) {
        int row = tid >> 2, seg = tid & 3;     // 256 threads -> one 16B seg each
        cp_async16(smb + PJ_WH + slot * 5120 + row * 80 + seg * 16,
                   g_Wh + (obase + row) * 256 + r * 32 + seg * 8);
        if (qk)
            cp_async16(smb + PJ_WL + slot * 5120 + row * 80 + seg * 16,
                       g_Wql + row * 256 + r * 32 + seg * 8);
        CP_COMMIT();
    };
    issueW(0, 0);
    issueW(1, 1);

    // ---- convert + transpose x tile: f32 (c,l) -> fp16 hi/lo [l][264] -------
    {
        const float* xb = x + ((size_t)n << 20) + l0;
        const int l = tid & 63, p0 = tid >> 6;     // p0 in 0..3
        #pragma unroll 4
        for (int i = 0; i < 32; i++) {
            int p = p0 + 4 * i;                    // c-pair index 0..127
            int c = 2 * p;
            float f0 = __ldg(&xb[(size_t)c * 4096 + l]);
            float f1 = __ldg(&xb[(size_t)(c + 1) * 4096 + l]);
            __half h0 = __float2half_rn(f0), h1 = __float2half_rn(f1);
            __half e0 = __float2half_rn(f0 - __half2float(h0));
            __half e1 = __float2half_rn(f1 - __half2float(h1));
            *(uint32_t*)(sm + PJ_XH + l * 528 + p * 4) = h2u(__halves2half2(h0, h1));
            *(uint32_t*)(sm + PJ_XL + l * 528 + p * 4) = h2u(__halves2half2(e0, e1));
        }
    }

    float C[4][4];
    #pragma unroll
    for (int og = 0; og < 4; og++)
        #pragma unroll
        for (int e = 0; e < 4; e++) C[og][e] = 0.f;

    const uint32_t aoffA = (uint32_t)((lane & 15) * 528 + (lane >> 4) * 16);
    const uint32_t aoffB = (uint32_t)((lane & 7) * 80 + (lane >> 3) * 16);
    const uint32_t abase = smb + (uint32_t)(wblk * 16) * 528;

    for (int r = 0; r < 8; r++) {
        const int slot = r % 3;
        if (r == 7) { CP_WAIT0(); } else { CP_WAIT1(); }
        __syncthreads();
        if (r + 2 < 8) issueW(r + 2, (r + 2) % 3);

        uint32_t axh0[4], axh1[4], axl0[4], axl1[4];
        ldsm_x4a(axh0, abase + PJ_XH + r * 64 + aoffA);
        ldsm_x4a(axh1, abase + PJ_XH + r * 64 + 32 + aoffA);
        ldsm_x4a(axl0, abase + PJ_XL + r * 64 + aoffA);
        ldsm_x4a(axl1, abase + PJ_XL + r * 64 + 32 + aoffA);

        const uint32_t wb  = smb + PJ_WH + slot * 5120;
        const uint32_t wlb = smb + PJ_WL + slot * 5120;
        #pragma unroll
        for (int ogl = 0; ogl < 4; ogl++) {
            const int og = wg * 4 + ogl;
            uint32_t b0, b1, b2, b3;
            ldsm_x4(b0, b1, b2, b3, wb + og * 640 + aoffB);
            mma_f16(C[ogl], axh0, b0, b1);
            mma_f16(C[ogl], axl0, b0, b1);
            mma_f16(C[ogl], axh1, b2, b3);
            mma_f16(C[ogl], axl1, b2, b3);
            if (qk) {
                uint32_t c0, c1, c2, c3;
                ldsm_x4(c0, c1, c2, c3, wlb + og * 640 + aoffB);
                mma_f16(C[ogl], axh0, c0, c1);
                mma_f16(C[ogl], axh1, c2, c3);
            }
        }
    }
    __syncthreads();

    if (qk) {
        #pragma unroll
        for (int ogl = 0; ogl < 4; ogl++) {
            const int og = wg * 4 + ogl;
            int ol = og * 8 + 2 * m;
            bool isq = (ol < 32);
            float sc = isq ? 1.0f : INVLN2;
            const float* bias = isq ? bq : bk;
            int bo = isq ? ol : ol - 32;
            float b0 = __ldg(&bias[bo]), b1 = __ldg(&bias[bo + 1]);
            uint32_t* dsth = (uint32_t*)(isq ? g_qh : g_kh);
            int col = (isq ? og * 4 : (og - 4) * 4) + m;
            #pragma unroll
            for (int rr = 0; rr < 2; rr++) {
                float f0 = (C[ogl][2 * rr]     + b0) * sc;
                float f1 = (C[ogl][2 * rr + 1] + b1) * sc;
                __half h0 = __float2half_rn(f0), h1 = __float2half_rn(f1);
                size_t lg = (size_t)(n << 12) + l0 + wblk * 16 + g + 8 * rr;
                dsth[lg * 16 + col] = h2u(__halves2half2(h0, h1));
                if (isq) {
                    __half e0 = __float2half_rn(f0 - __half2float(h0));
                    __half e1 = __float2half_rn(f1 - __half2float(h1));
                    ((uint32_t*)g_ql)[lg * 16 + col] = h2u(__halves2half2(e0, e1));
                }
            }
        }
    } else {
        __half* bo = (__half*)sm;            // [64 o][72 l]
        const int vb0 = (oidx - 1) * 64;
        #pragma unroll
        for (int ogl = 0; ogl < 4; ogl++) {
            const int og = wg * 4 + ogl;
            int ol = og * 8 + 2 * m;
            float b0 = __ldg(&bv[vb0 + ol]), b1 = __ldg(&bv[vb0 + ol + 1]);
            int lg = wblk * 16 + g;
            bo[ol * 72 + lg]           = __float2half_rn(C[ogl][0] + b0);
            bo[(ol + 1) * 72 + lg]     = __float2half_rn(C[ogl][1] + b1);
            bo[ol * 72 + lg + 8]       = __float2half_rn(C[ogl][2] + b0);
            bo[(ol + 1) * 72 + lg + 8] = __float2half_rn(C[ogl][3] + b1);
        }
        __syncthreads();
        const int o = tid >> 2, q = tid & 3;
        const uint4* src = (const uint4*)(sm + o * 144 + q * 32);
        uint4* dst = (uint4*)(g_v + (((size_t)(n * CC + vb0 + o)) << 12) + l0 + q * 16);
        dst[0] = src[0];
        dst[1] = src[1];
    }
}

// ---------------- kernel 3: BJ=64 skewed flash attention, 2-term S -----------
// S = (qh+ql)·kh : K residual dropped (error absorbed by output dilution).
#define OFF_QH 0            // [64][40] fp16
#define OFF_QL 5120
#define OFF_K  10240        // 2 slots x 5120: [KH 64][40]
#define OFF_V  20480        // 2 slots x 36864: [256][72] fp16
#define OFF_MB 94208        // full[0..1] at +0, empty[0..1] at +16
#define ATTN_SMEM 94464

__device__ __forceinline__ void loadK(uint32_t smb, int n, int j0, int slot, int tid) {
    const uint32_t kbase = smb + OFF_K + slot * 5120;
    #pragma unroll
    for (int it = 0; it < 2; it++) {
        int idx = it * 128 + tid;        // 0..255
        int r  = idx >> 2;               // 0..63
        int s  = idx & 3;
        const __half* src = g_kh + ((size_t)((n << 12) + j0 + r)) * 32 + s * 8;
        cp_async16(kbase + r * 80 + s * 16, src);
    }
}
__device__ __forceinline__ void loadV(uint32_t smb, int n, int j0, int slot, int tid) {
    const uint32_t vbase = smb + OFF_V + slot * 36864;
    #pragma unroll
    for (int it = 0; it < 16; it++) {
        int idx = it * 128 + tid;        // 0..2047
        int cr = idx >> 3;               // 0..255
        int s  = idx & 7;
        const __half* src = g_v + (((size_t)n * CC + cr) << 12) + j0 + s * 8;
        cp_async16(vbase + cr * 144 + s * 16, src);
    }
}

__global__ __launch_bounds__(128, 2)
void attn_kernel(const float* __restrict__ x,
                 const float* __restrict__ gamma,
                 float* __restrict__ out,
                 int n0) {
    extern __shared__ char sm[];
    const uint32_t smb = smem_u32(sm);
    const int tid  = threadIdx.x;
    const int wid  = tid >> 5, lane = tid & 31;
    const int g    = lane >> 2, m = lane & 3;
    const int iw   = wid * 16;
    const int n    = n0 + blockIdx.y;
    const int i0   = blockIdx.x * BI;

    const uint32_t aoffK = (uint32_t)((lane & 7) * 80 + (lane >> 3) * 16);
    const uint32_t aoffV = (uint32_t)((lane & 7) * 144 + (lane >> 3) * 16);
    const uint32_t mb_full  = smb + OFF_MB;
    const uint32_t mb_empty = smb + OFF_MB + 16;

    if (tid == 0) {
        #pragma unroll
        for (int s = 0; s < 2; s++) {
            MBARRIER_INIT(mb_full + 8 * s, 128);
            MBARRIER_INIT(mb_empty + 8 * s, 4);
        }
    }

    // ---- Q tile via plain ld/st ----
    #pragma unroll
    for (int it = 0; it < 4; it++) {
        int idx  = it * 128 + tid;          // 0..511
        int half = idx >> 8;
        int r    = (idx >> 2) & 63;
        int s    = idx & 3;
        const __half* src = (half ? g_ql : g_qh) + ((size_t)((n << 12) + i0 + r)) * 32 + s * 8;
        uint4 v = *(const uint4*)src;
        *(uint4*)(sm + (half ? OFF_QL : OFF_QH) + r * 80 + s * 16) = v;
    }
    __syncthreads();   // mbarrier init + Q visible

    // ---- prologue: fill slots 0,1 (tiles 0,1) ----
    #pragma unroll
    for (int t = 0; t < 2; t++) {
        loadK(smb, n, t * BJ, t, tid);
        loadV(smb, n, t * BJ, t, tid);
        CP_MBAR_ARRIVE(mb_full + 8 * t);
    }

    // ---- Q fragments ----
    uint32_t qh[2][4], ql[2][4];
    {
        const uint32_t* QHw = (const uint32_t*)(sm + OFF_QH);
        const uint32_t* QLw = (const uint32_t*)(sm + OFF_QL);
        #pragma unroll
        for (int kc = 0; kc < 2; kc++) {
            qh[kc][0] = QHw[(iw + g)     * 20 + 8 * kc + m];
            qh[kc][1] = QHw[(iw + g + 8) * 20 + 8 * kc + m];
            qh[kc][2] = QHw[(iw + g)     * 20 + 8 * kc + 4 + m];
            qh[kc][3] = QHw[(iw + g + 8) * 20 + 8 * kc + 4 + m];
            ql[kc][0] = QLw[(iw + g)     * 20 + 8 * kc + m];
            ql[kc][1] = QLw[(iw + g + 8) * 20 + 8 * kc + m];
            ql[kc][2] = QLw[(iw + g)     * 20 + 8 * kc + 4 + m];
            ql[kc][3] = QLw[(iw + g + 8) * 20 + 8 * kc + 4 + m];
        }
    }

    float O[32][4];
    #pragma unroll
    for (int nt = 0; nt < 32; nt++)
        #pragma unroll
        for (int e = 0; e < 4; e++) O[nt][e] = 0.f;
    float mr0 = -1e30f, mr1 = -1e30f, lr0 = 0.f, lr1 = 0.f;

    for (int jt = 0; jt < NJT; jt++) {
        const int s = jt & 1;

        // ---- per-warp prefetch of tile jt+1 into the other slot ----
        if (jt >= 1 && jt + 1 < NJT) {
            const int t2 = jt + 1;
            const int s2 = t2 & 1;
            MBARRIER_WAIT_PARITY(mb_empty + 8 * s2, (uint32_t)(((t2 >> 1) - 1) & 1));
            loadK(smb, n, t2 * BJ, s2, tid);
            loadV(smb, n, t2 * BJ, s2, tid);
            CP_MBAR_ARRIVE(mb_full + 8 * s2);
        }

        // ---- wait data ----
        MBARRIER_WAIT_PARITY(mb_full + 8 * s, (uint32_t)((jt >> 1) & 1));

        // ---- S = (qh+ql)·kh, 64 j per tile (2-term split) ----
        const uint32_t kb = smb + OFF_K + s * 5120;
        float C[8][4];
        #pragma unroll
        for (int nt = 0; nt < 8; nt++) {
            C[nt][0] = C[nt][1] = C[nt][2] = C[nt][3] = 0.f;
            uint32_t h0, h1, h2, h3;
            ldsm_x4(h0, h1, h2, h3, kb + nt * 640 + aoffK);
            mma_f16(C[nt], qh[0], h0, h1);  mma_f16(C[nt], ql[0], h0, h1);
            mma_f16(C[nt], qh[1], h2, h3);  mma_f16(C[nt], ql[1], h2, h3);
        }

        // ---- softmax, exp2 domain ----
        float t0 = -1e30f, t1 = -1e30f;
        #pragma unroll
        for (int nt = 0; nt < 8; nt++) {
            t0 = fmaxf(t0, fmaxf(C[nt][0], C[nt][1]));
            t1 = fmaxf(t1, fmaxf(C[nt][2], C[nt][3]));
        }
        t0 = fmaxf(t0, __shfl_xor_sync(0xffffffffu, t0, 1));
        t0 = fmaxf(t0, __shfl_xor_sync(0xffffffffu, t0, 2));
        t1 = fmaxf(t1, __shfl_xor_sync(0xffffffffu, t1, 1));
        t1 = fmaxf(t1, __shfl_xor_sync(0xffffffffu, t1, 2));
        float mn0 = fmaxf(mr0, t0), mn1 = fmaxf(mr1, t1);
        float al0 = ex2f(mr0 - mn0), al1 = ex2f(mr1 - mn1);
        mr0 = mn0; mr1 = mn1;

        uint32_t P[8][2];
        float rs0 = 0.f, rs1 = 0.f;
        #pragma unroll
        for (int nt = 0; nt < 8; nt++) {
            float p0 = ex2f(C[nt][0] - mn0), p1 = ex2f(C[nt][1] - mn0);
            float p2 = ex2f(C[nt][2] - mn1), p3 = ex2f(C[nt][3] - mn1);
            __half2 h01 = __floats2half2_rn(p0, p1);
            __half2 h23 = __floats2half2_rn(p2, p3);
            P[nt][0] = h2u(h01); P[nt][1] = h2u(h23);
            float2 f01 = __half22float2(h01), f23 = __half22float2(h23);
            rs0 += f01.x + f01.y; rs1 += f23.x + f23.y;
        }
        rs0 += __shfl_xor_sync(0xffffffffu, rs0, 1);
        rs0 += __shfl_xor_sync(0xffffffffu, rs0, 2);
        rs1 += __shfl_xor_sync(0xffffffffu, rs1, 1);
        rs1 += __shfl_xor_sync(0xffffffffu, rs1, 2);
        lr0 = lr0 * al0 + rs0;
        lr1 = lr1 * al1 + rs1;

        if (__any_sync(0xffffffffu, (al0 != 1.f) || (al1 != 1.f))) {
            #pragma unroll
            for (int nt = 0; nt < 32; nt++) {
                O[nt][0] *= al0; O[nt][1] *= al0;
                O[nt][2] *= al1; O[nt][3] *= al1;
            }
        }

        // ---- O += P V  (64 j = 4 k-chunks of 16, f32 accum) ----
        uint32_t pa[4][4];
        #pragma unroll
        for (int kc = 0; kc < 4; kc++) {
            pa[kc][0] = P[2 * kc][0];     pa[kc][1] = P[2 * kc][1];
            pa[kc][2] = P[2 * kc + 1][0]; pa[kc][3] = P[2 * kc + 1][1];
        }
        const uint32_t vb = smb + OFF_V + s * 36864;
        #pragma unroll
        for (int nt = 0; nt < 32; nt++) {
            uint32_t b00, b01, b10, b11, c00, c01, c10, c11;
            ldsm_x4(b00, b01, b10, b11, vb + nt * 1152 + aoffV);
            ldsm_x4(c00, c01, c10, c11, vb + nt * 1152 + 64 + aoffV);
            mma_f16(O[nt], pa[0], b00, b01);
            mma_f16(O[nt], pa[1], b10, b11);
            mma_f16(O[nt], pa[2], c00, c01);
            mma_f16(O[nt], pa[3], c10, c11);
        }

        // ---- this warp done reading slot s ----
        __syncwarp();
        if (lane == 0) MBAR_ARRIVE(mb_empty + 8 * s);
    }

    // ---- epilogue ----
    const float linv0 = 1.0f / lr0;
    const float linv1 = 1.0f / lr1;
    const float gam = __ldg(gamma);
    #pragma unroll
    for (int nt = 0; nt < 32; nt++) {
        #pragma unroll
        for (int e = 0; e < 4; e++) {
            int c   = 8 * nt + 2 * m + (e & 1);
            int row = iw + g + 8 * (e >> 1);
            size_t idx = (((size_t)(n * CC + c)) << 12) + i0 + row;
            float o = O[nt][e] * ((e >> 1) ? linv1 : linv0);
            out[idx] = gam * o + __ldg(&x[idx]);
        }
    }
}

// ---------------- launch: two-stream batch-split pipeline --------------------
extern "C" void kernel_launch(void* const* d_in, const int* in_sizes, int n_in,
                              void* d_out, int out_size) {
    const float* x     = (const float*)d_in[0];
    const float* Wq    = (const float*)d_in[1];
    const float* bq    = (const float*)d_in[2];
    const float* Wk    = (const float*)d_in[3];
    const float* bk    = (const float*)d_in[4];
    const float* Wv    = (const float*)d_in[5];
    const float* bv    = (const float*)d_in[6];
    const float* gamma = (const float*)d_in[7];
    float* out = (float*)d_out;

    cudaFuncSetAttribute(proj_kernel, cudaFuncAttributeMaxDynamicSharedMemorySize, PROJ_SMEM);
    cudaFuncSetAttribute(attn_kernel, cudaFuncAttributeMaxDynamicSharedMemorySize, ATTN_SMEM);

    cudaStream_t s2;
    cudaEvent_t ev0, ev2;
    cudaStreamCreateWithFlags(&s2, cudaStreamNonBlocking);
    cudaEventCreateWithFlags(&ev0, cudaEventDisableTiming);
    cudaEventCreateWithFlags(&ev2, cudaEventDisableTiming);

    const int HB = NB / 2;   // 4 batches per half

    // main (legacy) stream: wtrans -> fork -> half A
    wtrans_kernel<<<320, 256>>>(Wq, Wk, Wv);
    cudaEventRecord(ev0, 0);

    // branch B on s2
    cudaStreamWaitEvent(s2, ev0, 0);
    proj_kernel<<<dim3(LL / 64, 5, HB), 256, PROJ_SMEM, s2>>>(x, bq, bk, bv, HB);
    attn_kernel<<<dim3(LL / BI, HB), 128, ATTN_SMEM, s2>>>(x, gamma, out, HB);
    cudaEventRecord(ev2, s2);

    // branch A on main stream
    proj_kernel<<<dim3(LL / 64, 5, HB), 256, PROJ_SMEM>>>(x, bq, bk, bv, 0);
    attn_kernel<<<dim3(LL / BI, HB), 128, ATTN_SMEM>>>(x, gamma, out, 0);

    // join
    cudaStreamWaitEvent(0, ev2, 0);

    cudaEventDestroy(ev0);
    cudaEventDestroy(ev2);
    cudaStreamDestroy(s2);
}